// round 1
// baseline (speedup 1.0000x reference)
#include <cuda_runtime.h>
#include <cuda_bf16.h>
#include <cstdint>

// Problem constants
#define DIM      2048
#define KVDIM    512
#define SEQ      2048
#define BATCH    2
#define NHEADS   32
#define NKVHEADS 8
#define HD       64
#define ROWS     (BATCH * SEQ)   // 4096

// -------- scratch (static device memory; no allocations allowed) --------
__device__ float g_Q[ROWS * DIM];     // 33.5 MB
__device__ float g_K[ROWS * KVDIM];   //  8.4 MB
__device__ float g_V[ROWS * KVDIM];   //  8.4 MB
__device__ float g_O[ROWS * DIM];     // 33.5 MB

// ============================================================================
// SGEMM: C[M,N] = A[M,K] * B[K,N], all row-major fp32.
// 128x128 block tile, BK=16, 256 threads, 8x8 per-thread register tile.
// M,N multiples of 128; K multiple of 16 (holds for all our shapes).
// ============================================================================
#define BM 128
#define BN 128
#define BK 16
#define TM 8
#define TN 8

__global__ __launch_bounds__(256) void sgemm_kernel(
    int M, int N, int K,
    const float* __restrict__ A, const float* __restrict__ B,
    float* __restrict__ C)
{
    const int cRow = blockIdx.y;
    const int cCol = blockIdx.x;

    __shared__ float As[BK][BM];   // transposed A tile
    __shared__ float Bs[BK][BN];

    const int tid = threadIdx.x;
    const int threadCol = tid % (BN / TN);   // 0..15
    const int threadRow = tid / (BN / TN);   // 0..15

    A += (long)cRow * BM * K;
    B += (long)cCol * BN;
    C += (long)cRow * BM * N + (long)cCol * BN;

    // A loader: float4 along K
    const int innerRowA = tid / (BK / 4);    // 0..63
    const int innerColA = tid % (BK / 4);    // 0..3
    const int strideA   = 256 / (BK / 4);    // 64
    // B loader: float4 along N
    const int innerRowB = tid / (BN / 4);    // 0..7
    const int innerColB = tid % (BN / 4);    // 0..31
    const int strideB   = 256 / (BN / 4);    // 8

    float acc[TM * TN];
    #pragma unroll
    for (int i = 0; i < TM * TN; i++) acc[i] = 0.0f;
    float regM[TM], regN[TN];

    for (int bk = 0; bk < K; bk += BK) {
        #pragma unroll
        for (int off = 0; off < BM; off += strideA) {
            float4 t = *reinterpret_cast<const float4*>(
                &A[(long)(innerRowA + off) * K + innerColA * 4]);
            As[innerColA * 4 + 0][innerRowA + off] = t.x;
            As[innerColA * 4 + 1][innerRowA + off] = t.y;
            As[innerColA * 4 + 2][innerRowA + off] = t.z;
            As[innerColA * 4 + 3][innerRowA + off] = t.w;
        }
        #pragma unroll
        for (int off = 0; off < BK; off += strideB) {
            *reinterpret_cast<float4*>(&Bs[innerRowB + off][innerColB * 4]) =
                *reinterpret_cast<const float4*>(
                    &B[(long)(innerRowB + off) * N + innerColB * 4]);
        }
        __syncthreads();

        A += BK;
        B += (long)BK * N;

        #pragma unroll
        for (int k = 0; k < BK; k++) {
            #pragma unroll
            for (int i = 0; i < TM; i++) regM[i] = As[k][threadRow * TM + i];
            #pragma unroll
            for (int j = 0; j < TN; j++) regN[j] = Bs[k][threadCol * TN + j];
            #pragma unroll
            for (int i = 0; i < TM; i++)
                #pragma unroll
                for (int j = 0; j < TN; j++)
                    acc[i * TN + j] += regM[i] * regN[j];
        }
        __syncthreads();
    }

    #pragma unroll
    for (int i = 0; i < TM; i++) {
        #pragma unroll
        for (int j = 0; j < TN; j += 4) {
            float4 t;
            t.x = acc[i * TN + j + 0];
            t.y = acc[i * TN + j + 1];
            t.z = acc[i * TN + j + 2];
            t.w = acc[i * TN + j + 3];
            *reinterpret_cast<float4*>(
                &C[(long)(threadRow * TM + i) * N + threadCol * TN + j]) = t;
        }
    }
}

// ============================================================================
// Flash-attention (non-causal, full softmax over 2048 keys).
// Grid: (qtile=32, head=32, batch=2). Block: 256 threads (16x16).
// Each block: 64 query rows x head_dim 64, streams 64-row K/V tiles.
// Online softmax; 4x4 register accumulator per thread.
// Dynamic smem: Qs/Ks/Vs/Ps each [64][65] + 3*64 stats floats.
// ============================================================================
#define QT 64
#define KT 64
#define SROW 65   // padded row stride (floats) -> conflict-free

#define ATTN_SMEM_FLOATS (4 * QT * SROW + 3 * QT)
#define ATTN_SMEM_BYTES  (ATTN_SMEM_FLOATS * 4)

__global__ __launch_bounds__(256) void attn_kernel(
    const float* __restrict__ Q,   // [ROWS, DIM]
    const float* __restrict__ Kb,  // [ROWS, KVDIM]
    const float* __restrict__ Vb,  // [ROWS, KVDIM]
    float* __restrict__ O)         // [ROWS, DIM]
{
    extern __shared__ float sm[];
    float (*Qs)[SROW] = reinterpret_cast<float(*)[SROW]>(sm);
    float (*Ks)[SROW] = reinterpret_cast<float(*)[SROW]>(sm + QT * SROW);
    float (*Vs)[SROW] = reinterpret_cast<float(*)[SROW]>(sm + 2 * QT * SROW);
    float (*Ps)[SROW] = reinterpret_cast<float(*)[SROW]>(sm + 3 * QT * SROW);
    float* m_s     = sm + 4 * QT * SROW;
    float* l_s     = m_s + QT;
    float* alpha_s = l_s + QT;

    const int qt = blockIdx.x;
    const int h  = blockIdx.y;
    const int b  = blockIdx.z;
    const int kvh = h >> 2;                 // num_rep = 4

    const int tid = threadIdx.x;
    const int ty  = tid >> 4;               // 0..15
    const int tx  = tid & 15;               // 0..15

    // ---- load Q tile [64 x 64] ----
    for (int i = tid; i < QT * (HD / 4); i += 256) {
        const int r  = i >> 4;
        const int c4 = i & 15;
        const float4 t = *reinterpret_cast<const float4*>(
            Q + (long)(b * SEQ + qt * QT + r) * DIM + h * HD + c4 * 4);
        Qs[r][c4 * 4 + 0] = t.x;
        Qs[r][c4 * 4 + 1] = t.y;
        Qs[r][c4 * 4 + 2] = t.z;
        Qs[r][c4 * 4 + 3] = t.w;
    }
    if (tid < QT) { m_s[tid] = -1e30f; l_s[tid] = 0.0f; }

    float acc[4][4];
    #pragma unroll
    for (int i = 0; i < 4; i++)
        #pragma unroll
        for (int j = 0; j < 4; j++) acc[i][j] = 0.0f;

    __syncthreads();

    const float scale = 0.125f;  // 1/sqrt(64)

    for (int kt = 0; kt < SEQ / KT; kt++) {
        // ---- load K and V tiles [64 x 64] ----
        for (int i = tid; i < KT * (HD / 4); i += 256) {
            const int r  = i >> 4;
            const int c4 = i & 15;
            const long gofs = (long)(b * SEQ + kt * KT + r) * KVDIM + kvh * HD + c4 * 4;
            const float4 tk = *reinterpret_cast<const float4*>(Kb + gofs);
            Ks[r][c4 * 4 + 0] = tk.x;
            Ks[r][c4 * 4 + 1] = tk.y;
            Ks[r][c4 * 4 + 2] = tk.z;
            Ks[r][c4 * 4 + 3] = tk.w;
            const float4 tv = *reinterpret_cast<const float4*>(Vb + gofs);
            Vs[r][c4 * 4 + 0] = tv.x;
            Vs[r][c4 * 4 + 1] = tv.y;
            Vs[r][c4 * 4 + 2] = tv.z;
            Vs[r][c4 * 4 + 3] = tv.w;
        }
        __syncthreads();

        // ---- S = scale * Q K^T  (4x4 per thread) ----
        float s[4][4];
        #pragma unroll
        for (int i = 0; i < 4; i++)
            #pragma unroll
            for (int j = 0; j < 4; j++) s[i][j] = 0.0f;

        #pragma unroll 8
        for (int k = 0; k < HD; k++) {
            float qv[4], kv[4];
            #pragma unroll
            for (int i = 0; i < 4; i++) qv[i] = Qs[ty * 4 + i][k];
            #pragma unroll
            for (int j = 0; j < 4; j++) kv[j] = Ks[tx * 4 + j][k];
            #pragma unroll
            for (int i = 0; i < 4; i++)
                #pragma unroll
                for (int j = 0; j < 4; j++) s[i][j] += qv[i] * kv[j];
        }
        #pragma unroll
        for (int i = 0; i < 4; i++)
            #pragma unroll
            for (int j = 0; j < 4; j++)
                Ps[ty * 4 + i][tx * 4 + j] = s[i][j] * scale;
        __syncthreads();

        // ---- per-row online softmax update (64 threads, one per row) ----
        if (tid < QT) {
            const int r = tid;
            const float m_old = m_s[r];
            float mnew = m_old;
            #pragma unroll 8
            for (int k = 0; k < KT; k++) mnew = fmaxf(mnew, Ps[r][k]);
            float sum = 0.0f;
            #pragma unroll 8
            for (int k = 0; k < KT; k++) {
                const float p = __expf(Ps[r][k] - mnew);
                Ps[r][k] = p;
                sum += p;
            }
            const float alpha = __expf(m_old - mnew);
            l_s[r] = l_s[r] * alpha + sum;
            m_s[r] = mnew;
            alpha_s[r] = alpha;
        }
        __syncthreads();

        // ---- O = O*alpha + P V ----
        float al[4];
        #pragma unroll
        for (int i = 0; i < 4; i++) al[i] = alpha_s[ty * 4 + i];
        #pragma unroll
        for (int i = 0; i < 4; i++)
            #pragma unroll
            for (int j = 0; j < 4; j++) acc[i][j] *= al[i];

        #pragma unroll 8
        for (int k = 0; k < KT; k++) {
            float pv[4], vv[4];
            #pragma unroll
            for (int i = 0; i < 4; i++) pv[i] = Ps[ty * 4 + i][k];
            #pragma unroll
            for (int j = 0; j < 4; j++) vv[j] = Vs[k][tx * 4 + j];
            #pragma unroll
            for (int i = 0; i < 4; i++)
                #pragma unroll
                for (int j = 0; j < 4; j++) acc[i][j] += pv[i] * vv[j];
        }
        __syncthreads();
    }

    // ---- finalize: O /= l, write out ----
    float linv[4];
    #pragma unroll
    for (int i = 0; i < 4; i++) linv[i] = 1.0f / l_s[ty * 4 + i];

    #pragma unroll
    for (int i = 0; i < 4; i++) {
        float* op = O + (long)(b * SEQ + qt * QT + ty * 4 + i) * DIM + h * HD + tx * 4;
        #pragma unroll
        for (int j = 0; j < 4; j++) op[j] = acc[i][j] * linv[i];
    }
}

// ============================================================================
// kernel_launch
// ============================================================================
extern "C" void kernel_launch(void* const* d_in, const int* in_sizes, int n_in,
                              void* d_out, int out_size)
{
    const float* x  = (const float*)d_in[0];
    const float* Wq = (const float*)d_in[1];
    const float* Wk = (const float*)d_in[2];
    const float* Wv = (const float*)d_in[3];
    const float* Wo = (const float*)d_in[4];
    float* out = (float*)d_out;

    void *pq, *pk, *pv, *po;
    cudaGetSymbolAddress(&pq, g_Q);
    cudaGetSymbolAddress(&pk, g_K);
    cudaGetSymbolAddress(&pv, g_V);
    cudaGetSymbolAddress(&po, g_O);
    float* Qb = (float*)pq;
    float* Kb = (float*)pk;
    float* Vb = (float*)pv;
    float* Ob = (float*)po;

    cudaFuncSetAttribute(attn_kernel,
                         cudaFuncAttributeMaxDynamicSharedMemorySize,
                         ATTN_SMEM_BYTES);

    // Q = x @ Wq    [4096,2048] x [2048,2048]
    {
        dim3 grid(DIM / BN, ROWS / BM);
        sgemm_kernel<<<grid, 256>>>(ROWS, DIM, DIM, x, Wq, Qb);
    }
    // K = x @ Wk    [4096,2048] x [2048,512]
    {
        dim3 grid(KVDIM / BN, ROWS / BM);
        sgemm_kernel<<<grid, 256>>>(ROWS, KVDIM, DIM, x, Wk, Kb);
    }
    // V = x @ Wv
    {
        dim3 grid(KVDIM / BN, ROWS / BM);
        sgemm_kernel<<<grid, 256>>>(ROWS, KVDIM, DIM, x, Wv, Vb);
    }
    // attention
    {
        dim3 grid(SEQ / QT, NHEADS, BATCH);
        attn_kernel<<<grid, 256, ATTN_SMEM_BYTES>>>(Qb, Kb, Vb, Ob);
    }
    // out = O @ Wo  [4096,2048] x [2048,2048]
    {
        dim3 grid(DIM / BN, ROWS / BM);
        sgemm_kernel<<<grid, 256>>>(ROWS, DIM, DIM, Ob, Wo, out);
    }
}

// round 2
// speedup vs baseline: 2.1559x; 2.1559x over previous
#include <cuda_runtime.h>
#include <cuda_bf16.h>
#include <cstdint>

#define DIM      2048
#define KVDIM    512
#define SEQ      2048
#define BATCH    2
#define NHEADS   32
#define HD       64
#define ROWS     (BATCH * SEQ)   // 4096

// -------- scratch (static device memory; no allocations allowed) --------
__device__ float g_Q[ROWS * DIM];
__device__ float g_K[ROWS * KVDIM];
__device__ float g_V[ROWS * KVDIM];
__device__ float g_O[ROWS * DIM];

// ============================================================================
// helpers: ldmatrix / mma / fp32 -> bf16 hi+lo split
// ============================================================================
__device__ __forceinline__ uint32_t smem_u32(const void* p) {
    return (uint32_t)__cvta_generic_to_shared(p);
}
__device__ __forceinline__ void ldsm_x4(uint32_t* r, uint32_t addr) {
    asm volatile("ldmatrix.sync.aligned.m8n8.x4.shared.b16 {%0,%1,%2,%3}, [%4];"
                 : "=r"(r[0]), "=r"(r[1]), "=r"(r[2]), "=r"(r[3]) : "r"(addr));
}
__device__ __forceinline__ void ldsm_x2(uint32_t* r, uint32_t addr) {
    asm volatile("ldmatrix.sync.aligned.m8n8.x2.shared.b16 {%0,%1}, [%2];"
                 : "=r"(r[0]), "=r"(r[1]) : "r"(addr));
}
__device__ __forceinline__ void ldsm_x2t(uint32_t* r, uint32_t addr) {
    asm volatile("ldmatrix.sync.aligned.m8n8.x2.trans.shared.b16 {%0,%1}, [%2];"
                 : "=r"(r[0]), "=r"(r[1]) : "r"(addr));
}
__device__ __forceinline__ void mma16816(float* c, const uint32_t* a, const uint32_t* b) {
    asm volatile(
        "mma.sync.aligned.m16n8k16.row.col.f32.bf16.bf16.f32 "
        "{%0,%1,%2,%3}, {%4,%5,%6,%7}, {%8,%9}, {%0,%1,%2,%3};"
        : "+f"(c[0]), "+f"(c[1]), "+f"(c[2]), "+f"(c[3])
        : "r"(a[0]), "r"(a[1]), "r"(a[2]), "r"(a[3]), "r"(b[0]), "r"(b[1]));
}
__device__ __forceinline__ uint32_t packbf(float a, float b) {
    __nv_bfloat162 t = __floats2bfloat162_rn(a, b);
    return *reinterpret_cast<uint32_t*>(&t);
}
// split a float4 into hi/lo bf16 and store 4 consecutive elements (idx % 4 == 0)
__device__ __forceinline__ void split4(__nv_bfloat16* hi, __nv_bfloat16* lo,
                                       int idx, float4 v) {
    __nv_bfloat162 h01 = __floats2bfloat162_rn(v.x, v.y);
    __nv_bfloat162 h23 = __floats2bfloat162_rn(v.z, v.w);
    float r0 = v.x - __bfloat162float(h01.x);
    float r1 = v.y - __bfloat162float(h01.y);
    float r2 = v.z - __bfloat162float(h23.x);
    float r3 = v.w - __bfloat162float(h23.y);
    *reinterpret_cast<__nv_bfloat162*>(hi + idx)     = h01;
    *reinterpret_cast<__nv_bfloat162*>(hi + idx + 2) = h23;
    *reinterpret_cast<__nv_bfloat162*>(lo + idx)     = __floats2bfloat162_rn(r0, r1);
    *reinterpret_cast<__nv_bfloat162*>(lo + idx + 2) = __floats2bfloat162_rn(r2, r3);
}

// ============================================================================
// Split-bf16 GEMM: C[M,N] = A[M,K] * B[K,N], fp32 in/out, 3-product bf16 mma.
// Block tile 128x128, BK=32, 256 threads (8 warps, 2x4), warp tile 64x32.
// ============================================================================
#define ASTR 40    // padded smem stride (bf16 elems) for 32-wide A tile
#define BSTR 136   // padded smem stride for 128-wide B tile

__global__ __launch_bounds__(256) void gemm_bf16split(
    int N, int K,
    const float* __restrict__ A, const float* __restrict__ B,
    float* __restrict__ C)
{
    __shared__ __nv_bfloat16 Ah[128 * ASTR], Al[128 * ASTR];
    __shared__ __nv_bfloat16 Bh[32 * BSTR],  Bl[32 * BSTR];

    const int tid  = threadIdx.x;
    const int lane = tid & 31;
    const int warp = tid >> 5;
    const int wm   = warp >> 2;     // 0..1
    const int wn   = warp & 3;      // 0..3
    const long M0  = (long)blockIdx.y * 128;
    const long N0  = (long)blockIdx.x * 128;

    float c[4][4][4];
    #pragma unroll
    for (int i = 0; i < 4; i++)
        #pragma unroll
        for (int j = 0; j < 4; j++)
            #pragma unroll
            for (int e = 0; e < 4; e++) c[i][j][e] = 0.0f;

    // loader mapping
    const int ar = tid >> 1;            // A row 0..127 (2 threads/row)
    const int ac = (tid & 1) * 16;      // A col start (16 floats each)
    const int br = tid >> 3;            // B row 0..31  (8 threads/row)
    const int bc = (tid & 7) * 16;      // B col start (16 floats each)

    const uint32_t sAh = smem_u32(Ah), sAl = smem_u32(Al);
    const uint32_t sBh = smem_u32(Bh), sBl = smem_u32(Bl);

    for (int k0 = 0; k0 < K; k0 += 32) {
        const float* Ap = A + (M0 + ar) * (long)K + k0 + ac;
        #pragma unroll
        for (int i = 0; i < 4; i++) {
            float4 v = *reinterpret_cast<const float4*>(Ap + i * 4);
            split4(Ah, Al, ar * ASTR + ac + i * 4, v);
        }
        const float* Bp = B + (long)(k0 + br) * N + N0 + bc;
        #pragma unroll
        for (int i = 0; i < 4; i++) {
            float4 v = *reinterpret_cast<const float4*>(Bp + i * 4);
            split4(Bh, Bl, br * BSTR + bc + i * 4, v);
        }
        __syncthreads();

        #pragma unroll
        for (int kk = 0; kk < 32; kk += 16) {
            uint32_t ah[4][4], al[4][4], bh[4][2], bl[4][2];
            #pragma unroll
            for (int i = 0; i < 4; i++) {
                int row = wm * 64 + i * 16 + (lane & 15);
                int col = kk + (lane >> 4) * 8;
                uint32_t off = (uint32_t)(row * ASTR + col) * 2;
                ldsm_x4(ah[i], sAh + off);
                ldsm_x4(al[i], sAl + off);
            }
            #pragma unroll
            for (int j = 0; j < 4; j++) {
                int row = kk + (lane & 15);
                int col = wn * 32 + j * 8;
                uint32_t off = (uint32_t)(row * BSTR + col) * 2;
                ldsm_x2t(bh[j], sBh + off);
                ldsm_x2t(bl[j], sBl + off);
            }
            #pragma unroll
            for (int i = 0; i < 4; i++)
                #pragma unroll
                for (int j = 0; j < 4; j++) {
                    mma16816(c[i][j], ah[i], bh[j]);
                    mma16816(c[i][j], ah[i], bl[j]);
                    mma16816(c[i][j], al[i], bh[j]);
                }
        }
        __syncthreads();
    }

    // epilogue: fp32 store
    #pragma unroll
    for (int i = 0; i < 4; i++) {
        long r0 = M0 + wm * 64 + i * 16 + (lane >> 2);
        #pragma unroll
        for (int j = 0; j < 4; j++) {
            long cc = N0 + wn * 32 + j * 8 + 2 * (lane & 3);
            *reinterpret_cast<float2*>(&C[r0 * N + cc]) =
                make_float2(c[i][j][0], c[i][j][1]);
            *reinterpret_cast<float2*>(&C[(r0 + 8) * N + cc]) =
                make_float2(c[i][j][2], c[i][j][3]);
        }
    }
}

// ============================================================================
// Flash attention with split-bf16 mma.
// Block: 128 threads (4 warps). Each block: 64 q-rows of one (b,h);
// each warp owns 16 q-rows. Streams 64-key K/V tiles.
// smem tiles 64x64 bf16, padded stride 72 (conflict-free ldmatrix).
// ============================================================================
#define TSTR 72
#define ATTN_SMEM_BYTES (6 * 64 * TSTR * 2)   // Qh Ql Kh Kl Vh Vl

__global__ __launch_bounds__(128) void attn_mma(
    const float* __restrict__ Qg, const float* __restrict__ Kg,
    const float* __restrict__ Vg, float* __restrict__ Og)
{
    extern __shared__ __nv_bfloat16 dsm[];
    __nv_bfloat16* Qh = dsm;
    __nv_bfloat16* Ql = Qh + 64 * TSTR;
    __nv_bfloat16* Kh = Ql + 64 * TSTR;
    __nv_bfloat16* Kl = Kh + 64 * TSTR;
    __nv_bfloat16* Vh = Kl + 64 * TSTR;
    __nv_bfloat16* Vl = Vh + 64 * TSTR;

    const int tid  = threadIdx.x;
    const int lane = tid & 31;
    const int warp = tid >> 5;
    const int qt = blockIdx.x, h = blockIdx.y, b = blockIdx.z;
    const int kvh = h >> 2;   // 4 q-heads per kv-head

    const uint32_t sQh = smem_u32(Qh), sQl = smem_u32(Ql);
    const uint32_t sKh = smem_u32(Kh), sKl = smem_u32(Kl);
    const uint32_t sVh = smem_u32(Vh), sVl = smem_u32(Vl);

    // ---- load Q tile (scaled by 1/sqrt(64)=0.125), split to hi/lo ----
    const int r     = tid >> 1;          // 0..63
    const int cbase = (tid & 1) * 32;    // 32 floats per thread per row
    {
        const float* Qp = Qg + (long)(b * SEQ + qt * 64 + r) * DIM + h * HD + cbase;
        #pragma unroll
        for (int i = 0; i < 8; i++) {
            float4 v = *reinterpret_cast<const float4*>(Qp + i * 4);
            v.x *= 0.125f; v.y *= 0.125f; v.z *= 0.125f; v.w *= 0.125f;
            split4(Qh, Ql, r * TSTR + cbase + i * 4, v);
        }
    }
    __syncthreads();

    // ---- Q fragments (A operand, 4 k-steps of 16) ----
    uint32_t qh[4][4], ql[4][4];
    #pragma unroll
    for (int t = 0; t < 4; t++) {
        int row = warp * 16 + (lane & 15);
        int col = t * 16 + (lane >> 4) * 8;
        uint32_t off = (uint32_t)(row * TSTR + col) * 2;
        ldsm_x4(qh[t], sQh + off);
        ldsm_x4(ql[t], sQl + off);
    }

    float o[8][4];
    #pragma unroll
    for (int j = 0; j < 8; j++)
        #pragma unroll
        for (int e = 0; e < 4; e++) o[j][e] = 0.0f;
    float m0v = -1e30f, m1v = -1e30f, l0 = 0.0f, l1 = 0.0f;

    for (int kt = 0; kt < SEQ / 64; kt++) {
        __syncthreads();   // previous iteration done reading smem
        // ---- load K/V tiles, split to hi/lo ----
        {
            const long gofs = (long)(b * SEQ + kt * 64 + r) * KVDIM + kvh * HD + cbase;
            const float* Kp = Kg + gofs;
            const float* Vp = Vg + gofs;
            #pragma unroll
            for (int i = 0; i < 8; i++) {
                float4 vk = *reinterpret_cast<const float4*>(Kp + i * 4);
                split4(Kh, Kl, r * TSTR + cbase + i * 4, vk);
                float4 vv = *reinterpret_cast<const float4*>(Vp + i * 4);
                split4(Vh, Vl, r * TSTR + cbase + i * 4, vv);
            }
        }
        __syncthreads();

        // ---- S = (Q/8) K^T : 8 n-tiles (keys), 4 k-steps, 3 products ----
        float s[8][4];
        #pragma unroll
        for (int j = 0; j < 8; j++)
            #pragma unroll
            for (int e = 0; e < 4; e++) s[j][e] = 0.0f;

        #pragma unroll
        for (int t = 0; t < 4; t++) {
            #pragma unroll
            for (int j = 0; j < 8; j++) {
                uint32_t kbh[2], kbl[2];
                int kl16 = lane & 15;
                int row = j * 8 + (kl16 & 7);
                int col = t * 16 + (kl16 >> 3) * 8;
                uint32_t off = (uint32_t)(row * TSTR + col) * 2;
                ldsm_x2(kbh, sKh + off);
                ldsm_x2(kbl, sKl + off);
                mma16816(s[j], qh[t], kbh);
                mma16816(s[j], qh[t], kbl);
                mma16816(s[j], ql[t], kbh);
            }
        }

        // ---- online softmax (two row-groups per thread) ----
        float tm0 = -1e30f, tm1 = -1e30f;
        #pragma unroll
        for (int j = 0; j < 8; j++) {
            tm0 = fmaxf(tm0, fmaxf(s[j][0], s[j][1]));
            tm1 = fmaxf(tm1, fmaxf(s[j][2], s[j][3]));
        }
        #pragma unroll
        for (int off = 1; off <= 2; off <<= 1) {
            tm0 = fmaxf(tm0, __shfl_xor_sync(0xffffffffu, tm0, off));
            tm1 = fmaxf(tm1, __shfl_xor_sync(0xffffffffu, tm1, off));
        }
        const float mn0 = fmaxf(m0v, tm0), mn1 = fmaxf(m1v, tm1);
        const float a0 = __expf(m0v - mn0), a1 = __expf(m1v - mn1);
        m0v = mn0; m1v = mn1;

        float sum0 = 0.0f, sum1 = 0.0f;
        #pragma unroll
        for (int j = 0; j < 8; j++) {
            s[j][0] = __expf(s[j][0] - mn0);
            s[j][1] = __expf(s[j][1] - mn0);
            s[j][2] = __expf(s[j][2] - mn1);
            s[j][3] = __expf(s[j][3] - mn1);
            sum0 += s[j][0] + s[j][1];
            sum1 += s[j][2] + s[j][3];
        }
        #pragma unroll
        for (int off = 1; off <= 2; off <<= 1) {
            sum0 += __shfl_xor_sync(0xffffffffu, sum0, off);
            sum1 += __shfl_xor_sync(0xffffffffu, sum1, off);
        }
        l0 = l0 * a0 + sum0;
        l1 = l1 * a1 + sum1;
        #pragma unroll
        for (int j = 0; j < 8; j++) {
            o[j][0] *= a0; o[j][1] *= a0;
            o[j][2] *= a1; o[j][3] *= a1;
        }

        // ---- O += P V  (P split to hi/lo, V split in smem) ----
        #pragma unroll
        for (int t = 0; t < 4; t++) {
            // A-fragment directly from S accumulators (layout identity)
            float p00 = s[2*t][0],   p01 = s[2*t][1];
            float p02 = s[2*t][2],   p03 = s[2*t][3];
            float p10 = s[2*t+1][0], p11 = s[2*t+1][1];
            float p12 = s[2*t+1][2], p13 = s[2*t+1][3];
            uint32_t ph[4], pl[4];
            ph[0] = packbf(p00, p01); ph[1] = packbf(p02, p03);
            ph[2] = packbf(p10, p11); ph[3] = packbf(p12, p13);
            pl[0] = packbf(p00 - __bfloat162float(__float2bfloat16(p00)),
                           p01 - __bfloat162float(__float2bfloat16(p01)));
            pl[1] = packbf(p02 - __bfloat162float(__float2bfloat16(p02)),
                           p03 - __bfloat162float(__float2bfloat16(p03)));
            pl[2] = packbf(p10 - __bfloat162float(__float2bfloat16(p10)),
                           p11 - __bfloat162float(__float2bfloat16(p11)));
            pl[3] = packbf(p12 - __bfloat162float(__float2bfloat16(p12)),
                           p13 - __bfloat162float(__float2bfloat16(p13)));
            #pragma unroll
            for (int j = 0; j < 8; j++) {
                uint32_t vbh[2], vbl[2];
                int row = t * 16 + (lane & 15);
                int col = j * 8;
                uint32_t off = (uint32_t)(row * TSTR + col) * 2;
                ldsm_x2t(vbh, sVh + off);
                ldsm_x2t(vbl, sVl + off);
                mma16816(o[j], ph, vbh);
                mma16816(o[j], ph, vbl);
                mma16816(o[j], pl, vbh);
            }
        }
    }

    // ---- finalize + store ----
    const float il0 = 1.0f / l0, il1 = 1.0f / l1;
    const int row0 = qt * 64 + warp * 16 + (lane >> 2);
    const long base = (long)(b * SEQ + row0) * DIM + h * HD;
    #pragma unroll
    for (int j = 0; j < 8; j++) {
        const int col = j * 8 + 2 * (lane & 3);
        *reinterpret_cast<float2*>(&Og[base + col]) =
            make_float2(o[j][0] * il0, o[j][1] * il0);
        *reinterpret_cast<float2*>(&Og[base + (long)8 * DIM + col]) =
            make_float2(o[j][2] * il1, o[j][3] * il1);
    }
}

// ============================================================================
// kernel_launch
// ============================================================================
extern "C" void kernel_launch(void* const* d_in, const int* in_sizes, int n_in,
                              void* d_out, int out_size)
{
    const float* x  = (const float*)d_in[0];
    const float* Wq = (const float*)d_in[1];
    const float* Wk = (const float*)d_in[2];
    const float* Wv = (const float*)d_in[3];
    const float* Wo = (const float*)d_in[4];
    float* out = (float*)d_out;

    void *pq, *pk, *pv, *po;
    cudaGetSymbolAddress(&pq, g_Q);
    cudaGetSymbolAddress(&pk, g_K);
    cudaGetSymbolAddress(&pv, g_V);
    cudaGetSymbolAddress(&po, g_O);
    float* Qb = (float*)pq;
    float* Kb = (float*)pk;
    float* Vb = (float*)pv;
    float* Ob = (float*)po;

    cudaFuncSetAttribute(attn_mma,
                         cudaFuncAttributeMaxDynamicSharedMemorySize,
                         ATTN_SMEM_BYTES);

    // Q = x @ Wq
    gemm_bf16split<<<dim3(DIM / 128, ROWS / 128), 256>>>(DIM, DIM, x, Wq, Qb);
    // K = x @ Wk
    gemm_bf16split<<<dim3(KVDIM / 128, ROWS / 128), 256>>>(KVDIM, DIM, x, Wk, Kb);
    // V = x @ Wv
    gemm_bf16split<<<dim3(KVDIM / 128, ROWS / 128), 256>>>(KVDIM, DIM, x, Wv, Vb);
    // attention
    attn_mma<<<dim3(SEQ / 64, NHEADS, BATCH), 128, ATTN_SMEM_BYTES>>>(Qb, Kb, Vb, Ob);
    // out = O @ Wo
    gemm_bf16split<<<dim3(DIM / 128, ROWS / 128), 256>>>(DIM, DIM, Ob, Wo, out);
}

// round 3
// speedup vs baseline: 3.6062x; 1.6727x over previous
#include <cuda_runtime.h>
#include <cuda_bf16.h>
#include <cuda_fp16.h>
#include <cstdint>

#define DIM      2048
#define KVDIM    512
#define SEQ      2048
#define BATCH    2
#define NHEADS   32
#define HD       64
#define ROWS     (BATCH * SEQ)   // 4096

// -------- static scratch (no allocations allowed) --------
__device__ __nv_bfloat16 g_xh[ROWS * DIM],  g_xl[ROWS * DIM];
__device__ __nv_bfloat16 g_Wqh[DIM * DIM],  g_Wql[DIM * DIM];
__device__ __nv_bfloat16 g_Wkh[DIM * KVDIM], g_Wkl[DIM * KVDIM];
__device__ __nv_bfloat16 g_Wvh[DIM * KVDIM], g_Wvl[DIM * KVDIM];
__device__ __nv_bfloat16 g_Woh[DIM * DIM],  g_Wol[DIM * DIM];
__device__ __half        g_Qh[ROWS * DIM],  g_Ql[ROWS * DIM];   // pre-scaled by 0.125
__device__ __half        g_Kh[ROWS * KVDIM], g_Vh[ROWS * KVDIM];
__device__ __nv_bfloat16 g_Oh[ROWS * DIM],  g_Ol[ROWS * DIM];

// ============================================================================
// helpers
// ============================================================================
__device__ __forceinline__ uint32_t smem_u32(const void* p) {
    return (uint32_t)__cvta_generic_to_shared(p);
}
__device__ __forceinline__ void ldsm_x4(uint32_t* r, uint32_t addr) {
    asm volatile("ldmatrix.sync.aligned.m8n8.x4.shared.b16 {%0,%1,%2,%3}, [%4];"
                 : "=r"(r[0]), "=r"(r[1]), "=r"(r[2]), "=r"(r[3]) : "r"(addr));
}
__device__ __forceinline__ void ldsm_x4t(uint32_t* r, uint32_t addr) {
    asm volatile("ldmatrix.sync.aligned.m8n8.x4.trans.shared.b16 {%0,%1,%2,%3}, [%4];"
                 : "=r"(r[0]), "=r"(r[1]), "=r"(r[2]), "=r"(r[3]) : "r"(addr));
}
__device__ __forceinline__ void mma_bf(float* c, const uint32_t* a, const uint32_t* b) {
    asm volatile(
        "mma.sync.aligned.m16n8k16.row.col.f32.bf16.bf16.f32 "
        "{%0,%1,%2,%3}, {%4,%5,%6,%7}, {%8,%9}, {%0,%1,%2,%3};"
        : "+f"(c[0]), "+f"(c[1]), "+f"(c[2]), "+f"(c[3])
        : "r"(a[0]), "r"(a[1]), "r"(a[2]), "r"(a[3]), "r"(b[0]), "r"(b[1]));
}
__device__ __forceinline__ void mma_h(float* c, const uint32_t* a, const uint32_t* b) {
    asm volatile(
        "mma.sync.aligned.m16n8k16.row.col.f32.f16.f16.f32 "
        "{%0,%1,%2,%3}, {%4,%5,%6,%7}, {%8,%9}, {%0,%1,%2,%3};"
        : "+f"(c[0]), "+f"(c[1]), "+f"(c[2]), "+f"(c[3])
        : "r"(a[0]), "r"(a[1]), "r"(a[2]), "r"(a[3]), "r"(b[0]), "r"(b[1]));
}
__device__ __forceinline__ void cp16(uint32_t dst, const void* src) {
    asm volatile("cp.async.cg.shared.global [%0], [%1], 16;" :: "r"(dst), "l"(src));
}
__device__ __forceinline__ void cp_commit() { asm volatile("cp.async.commit_group;"); }
__device__ __forceinline__ void cp_wait0()  { asm volatile("cp.async.wait_group 0;"); }

__device__ __forceinline__ uint32_t packh(float a, float b) {
    __half2 t = __floats2half2_rn(a, b);
    return *reinterpret_cast<uint32_t*>(&t);
}
__device__ __forceinline__ float h_round(float x) {
    return __half2float(__float2half_rn(x));
}
// split a float4 into bf16 hi/lo, store 4 consecutive elements (idx % 4 == 0)
__device__ __forceinline__ void split4(__nv_bfloat16* hi, __nv_bfloat16* lo,
                                       long idx, float4 v) {
    __nv_bfloat162 h01 = __floats2bfloat162_rn(v.x, v.y);
    __nv_bfloat162 h23 = __floats2bfloat162_rn(v.z, v.w);
    float r0 = v.x - __bfloat162float(h01.x);
    float r1 = v.y - __bfloat162float(h01.y);
    float r2 = v.z - __bfloat162float(h23.x);
    float r3 = v.w - __bfloat162float(h23.y);
    *reinterpret_cast<__nv_bfloat162*>(hi + idx)     = h01;
    *reinterpret_cast<__nv_bfloat162*>(hi + idx + 2) = h23;
    *reinterpret_cast<__nv_bfloat162*>(lo + idx)     = __floats2bfloat162_rn(r0, r1);
    *reinterpret_cast<__nv_bfloat162*>(lo + idx + 2) = __floats2bfloat162_rn(r2, r3);
}

// ============================================================================
// elementwise pre-split: fp32 -> bf16 hi/lo
// ============================================================================
__global__ __launch_bounds__(256) void split_bf16(
    const float4* __restrict__ src, __nv_bfloat16* __restrict__ hi,
    __nv_bfloat16* __restrict__ lo, int n4)
{
    int i = blockIdx.x * 256 + threadIdx.x;
    if (i < n4) split4(hi, lo, (long)i * 4, src[i]);
}

// ============================================================================
// bf16 split GEMM with cp.async double buffering.
// C[M,N] = (Ah+Al)(Bh+Bl)  (3-product; AlBl dropped)
// Block tile 128x128, BK=32, 256 threads (8 warps 2x4), warp tile 64x32.
// EPI: 0=f32 out0 ; 2=fp16 split (out0=hi,out1=lo, scaled) ; 3=fp16 single
// ============================================================================
#define GASTR 40
#define GBSTR 136
#define G_ABYTES (128 * GASTR * 2)     // 10240
#define G_BBYTES (32 * GBSTR * 2)      //  8704
#define G_STAGE  (2 * G_ABYTES + 2 * G_BBYTES)   // 37888
#define G_SMEM   (2 * G_STAGE)                   // 75776

template<int EPI>
__global__ __launch_bounds__(256) void gemm_split(
    int N, int K,
    const __nv_bfloat16* __restrict__ Ah, const __nv_bfloat16* __restrict__ Al,
    const __nv_bfloat16* __restrict__ Bh, const __nv_bfloat16* __restrict__ Bl,
    void* __restrict__ out0, void* __restrict__ out1, float scale)
{
    extern __shared__ __align__(16) char gsm[];
    const uint32_t sbase = smem_u32(gsm);

    const int tid  = threadIdx.x;
    const int lane = tid & 31;
    const int warp = tid >> 5;
    const int wm   = warp >> 2;
    const int wn   = warp & 3;
    const long M0  = (long)blockIdx.y * 128;
    const long N0  = (long)blockIdx.x * 128;

    float c[4][4][4];
    #pragma unroll
    for (int i = 0; i < 4; i++)
        #pragma unroll
        for (int j = 0; j < 4; j++)
            #pragma unroll
            for (int e = 0; e < 4; e++) c[i][j][e] = 0.0f;

    auto loadStage = [&](int st, int k0) {
        uint32_t sA  = sbase + st * G_STAGE;
        uint32_t sAl = sA + G_ABYTES;
        uint32_t sB  = sA + 2 * G_ABYTES;
        uint32_t sBl = sB + G_BBYTES;
        #pragma unroll
        for (int i = 0; i < 2; i++) {
            int ci = tid + i * 256;
            int row = ci >> 2, c8 = ci & 3;
            uint32_t so = (uint32_t)(row * GASTR + c8 * 8) * 2;
            long go = (M0 + row) * (long)K + k0 + c8 * 8;
            cp16(sA + so, Ah + go);
            cp16(sAl + so, Al + go);
        }
        #pragma unroll
        for (int i = 0; i < 2; i++) {
            int ci = tid + i * 256;
            int row = ci >> 4, c8 = ci & 15;
            uint32_t so = (uint32_t)(row * GBSTR + c8 * 8) * 2;
            long go = (long)(k0 + row) * N + N0 + c8 * 8;
            cp16(sB + so, Bh + go);
            cp16(sBl + so, Bl + go);
        }
    };

    const int nk = K / 32;
    loadStage(0, 0);
    cp_commit();

    for (int kt = 0; kt < nk; kt++) {
        cp_wait0();
        __syncthreads();
        if (kt + 1 < nk) loadStage((kt + 1) & 1, (kt + 1) * 32);
        cp_commit();

        uint32_t sA  = sbase + (kt & 1) * G_STAGE;
        uint32_t sAl = sA + G_ABYTES;
        uint32_t sB  = sA + 2 * G_ABYTES;
        uint32_t sBl = sB + G_BBYTES;

        #pragma unroll
        for (int kk = 0; kk < 32; kk += 16) {
            uint32_t ah[4][4], al[4][4], bh[2][4], bl[2][4];
            #pragma unroll
            for (int i = 0; i < 4; i++) {
                int row = wm * 64 + i * 16 + (lane & 15);
                int col = kk + (lane >> 4) * 8;
                uint32_t off = (uint32_t)(row * GASTR + col) * 2;
                ldsm_x4(ah[i], sA + off);
                ldsm_x4(al[i], sAl + off);
            }
            #pragma unroll
            for (int jp = 0; jp < 2; jp++) {
                int row = kk + (lane & 15);
                int col = wn * 32 + jp * 16 + ((lane >> 4) << 3);
                uint32_t off = (uint32_t)(row * GBSTR + col) * 2;
                ldsm_x4t(bh[jp], sB + off);
                ldsm_x4t(bl[jp], sBl + off);
            }
            #pragma unroll
            for (int i = 0; i < 4; i++)
                #pragma unroll
                for (int jp = 0; jp < 2; jp++) {
                    mma_bf(c[i][2 * jp],     ah[i], bh[jp]);
                    mma_bf(c[i][2 * jp],     ah[i], bl[jp]);
                    mma_bf(c[i][2 * jp],     al[i], bh[jp]);
                    mma_bf(c[i][2 * jp + 1], ah[i], bh[jp] + 2);
                    mma_bf(c[i][2 * jp + 1], ah[i], bl[jp] + 2);
                    mma_bf(c[i][2 * jp + 1], al[i], bh[jp] + 2);
                }
        }
    }

    // epilogue
    #pragma unroll
    for (int i = 0; i < 4; i++) {
        long r0 = M0 + wm * 64 + i * 16 + (lane >> 2);
        #pragma unroll
        for (int j = 0; j < 4; j++) {
            long cc = N0 + wn * 32 + j * 8 + 2 * (lane & 3);
            float v0 = c[i][j][0] * scale, v1 = c[i][j][1] * scale;
            float v2 = c[i][j][2] * scale, v3 = c[i][j][3] * scale;
            if (EPI == 0) {
                float* C = (float*)out0;
                *reinterpret_cast<float2*>(&C[r0 * N + cc])       = make_float2(v0, v1);
                *reinterpret_cast<float2*>(&C[(r0 + 8) * N + cc]) = make_float2(v2, v3);
            } else if (EPI == 2) {
                __half* Ch = (__half*)out0;
                __half* Cl = (__half*)out1;
                float h0 = h_round(v0), h1 = h_round(v1);
                float h2 = h_round(v2), h3 = h_round(v3);
                *reinterpret_cast<uint32_t*>(&Ch[r0 * N + cc])       = packh(h0, h1);
                *reinterpret_cast<uint32_t*>(&Ch[(r0 + 8) * N + cc]) = packh(h2, h3);
                *reinterpret_cast<uint32_t*>(&Cl[r0 * N + cc])       = packh(v0 - h0, v1 - h1);
                *reinterpret_cast<uint32_t*>(&Cl[(r0 + 8) * N + cc]) = packh(v2 - h2, v3 - h3);
            } else { // EPI == 3
                __half* Ch = (__half*)out0;
                *reinterpret_cast<uint32_t*>(&Ch[r0 * N + cc])       = packh(v0, v1);
                *reinterpret_cast<uint32_t*>(&Ch[(r0 + 8) * N + cc]) = packh(v2, v3);
            }
        }
    }
}

// ============================================================================
// fp16 flash attention.
// Block 256 thr (8 warps), 128 q-rows of one (b,h); warp owns 16 rows.
// S = (Qh+Ql) K (Q pre-scaled fp16 split, K fp16) ; PV = (Ph+Pl) V.
// K/V double-buffered with cp.async. Output: bf16 hi/lo split.
// ============================================================================
#define TSTR 72
#define Q_BYTES  (128 * TSTR * 2)    // 18432 per tensor
#define KV_BYTES (64 * TSTR * 2)     //  9216 per tensor
#define A_STAGE  (2 * KV_BYTES)      // K + V per stage
#define ATTN_SMEM (2 * Q_BYTES + 2 * A_STAGE)   // 73728

__global__ __launch_bounds__(256) void attn_fp16(
    const __half* __restrict__ Qh_g, const __half* __restrict__ Ql_g,
    const __half* __restrict__ K_g,  const __half* __restrict__ V_g,
    __nv_bfloat16* __restrict__ Oh_g, __nv_bfloat16* __restrict__ Ol_g)
{
    extern __shared__ __align__(16) char smp[];
    const uint32_t sb  = smem_u32(smp);
    const uint32_t sQh = sb;
    const uint32_t sQl = sb + Q_BYTES;
    const uint32_t sKV = sb + 2 * Q_BYTES;

    const int tid  = threadIdx.x;
    const int lane = tid & 31;
    const int warp = tid >> 5;
    const int qt = blockIdx.x, h = blockIdx.y, b = blockIdx.z;
    const int kvh = h >> 2;

    auto loadKV = [&](int st, int kt) {
        uint32_t sK = sKV + st * A_STAGE;
        uint32_t sV = sK + KV_BYTES;
        #pragma unroll
        for (int i = 0; i < 2; i++) {
            int ci = tid + i * 256;
            int row = ci >> 3, c8 = ci & 7;
            uint32_t so = (uint32_t)(row * TSTR + c8 * 8) * 2;
            long go = (long)(b * SEQ + kt * 64 + row) * KVDIM + kvh * HD + c8 * 8;
            cp16(sK + so, K_g + go);
            cp16(sV + so, V_g + go);
        }
    };

    // prologue: Q + first K/V stage
    #pragma unroll
    for (int i = 0; i < 4; i++) {
        int ci = tid + i * 256;
        int row = ci >> 3, c8 = ci & 7;
        uint32_t so = (uint32_t)(row * TSTR + c8 * 8) * 2;
        long go = (long)(b * SEQ + qt * 128 + row) * DIM + h * HD + c8 * 8;
        cp16(sQh + so, Qh_g + go);
        cp16(sQl + so, Ql_g + go);
    }
    loadKV(0, 0);
    cp_commit();
    cp_wait0();
    __syncthreads();

    // Q fragments (pre-scaled)
    uint32_t qh[4][4], ql[4][4];
    #pragma unroll
    for (int t = 0; t < 4; t++) {
        int row = warp * 16 + (lane & 15);
        int col = t * 16 + (lane >> 4) * 8;
        uint32_t off = (uint32_t)(row * TSTR + col) * 2;
        ldsm_x4(qh[t], sQh + off);
        ldsm_x4(ql[t], sQl + off);
    }

    float o[8][4];
    #pragma unroll
    for (int j = 0; j < 8; j++)
        #pragma unroll
        for (int e = 0; e < 4; e++) o[j][e] = 0.0f;
    float m0v = -1e30f, m1v = -1e30f, l0 = 0.0f, l1 = 0.0f;

    for (int kt = 0; kt < SEQ / 64; kt++) {
        const int cur = kt & 1;
        if (kt + 1 < SEQ / 64) { loadKV(cur ^ 1, kt + 1); }
        cp_commit();

        const uint32_t sK = sKV + cur * A_STAGE;
        const uint32_t sV = sK + KV_BYTES;

        // ---- S = Q K^T ----
        float s[8][4];
        #pragma unroll
        for (int j = 0; j < 8; j++)
            #pragma unroll
            for (int e = 0; e < 4; e++) s[j][e] = 0.0f;

        const int l7 = lane & 7, g4 = lane >> 3;
        #pragma unroll
        for (int t = 0; t < 4; t++) {
            #pragma unroll
            for (int jp = 0; jp < 4; jp++) {
                uint32_t kb[4];
                int row = jp * 16 + ((g4 >> 1) << 3) + l7;
                int col = t * 16 + ((g4 & 1) << 3);
                ldsm_x4(kb, sK + (uint32_t)(row * TSTR + col) * 2);
                mma_h(s[2 * jp],     qh[t], kb);
                mma_h(s[2 * jp],     ql[t], kb);
                mma_h(s[2 * jp + 1], qh[t], kb + 2);
                mma_h(s[2 * jp + 1], ql[t], kb + 2);
            }
        }

        // ---- online softmax ----
        float tm0 = -1e30f, tm1 = -1e30f;
        #pragma unroll
        for (int j = 0; j < 8; j++) {
            tm0 = fmaxf(tm0, fmaxf(s[j][0], s[j][1]));
            tm1 = fmaxf(tm1, fmaxf(s[j][2], s[j][3]));
        }
        #pragma unroll
        for (int off = 1; off <= 2; off <<= 1) {
            tm0 = fmaxf(tm0, __shfl_xor_sync(0xffffffffu, tm0, off));
            tm1 = fmaxf(tm1, __shfl_xor_sync(0xffffffffu, tm1, off));
        }
        const float mn0 = fmaxf(m0v, tm0), mn1 = fmaxf(m1v, tm1);
        const float a0 = __expf(m0v - mn0), a1 = __expf(m1v - mn1);
        m0v = mn0; m1v = mn1;

        float sum0 = 0.0f, sum1 = 0.0f;
        #pragma unroll
        for (int j = 0; j < 8; j++) {
            s[j][0] = __expf(s[j][0] - mn0);
            s[j][1] = __expf(s[j][1] - mn0);
            s[j][2] = __expf(s[j][2] - mn1);
            s[j][3] = __expf(s[j][3] - mn1);
            sum0 += s[j][0] + s[j][1];
            sum1 += s[j][2] + s[j][3];
        }
        #pragma unroll
        for (int off = 1; off <= 2; off <<= 1) {
            sum0 += __shfl_xor_sync(0xffffffffu, sum0, off);
            sum1 += __shfl_xor_sync(0xffffffffu, sum1, off);
        }
        l0 = l0 * a0 + sum0;
        l1 = l1 * a1 + sum1;
        #pragma unroll
        for (int j = 0; j < 8; j++) {
            o[j][0] *= a0; o[j][1] *= a0;
            o[j][2] *= a1; o[j][3] *= a1;
        }

        // ---- O += P V ----
        #pragma unroll
        for (int t = 0; t < 4; t++) {
            float p00 = s[2 * t][0],     p01 = s[2 * t][1];
            float p02 = s[2 * t][2],     p03 = s[2 * t][3];
            float p10 = s[2 * t + 1][0], p11 = s[2 * t + 1][1];
            float p12 = s[2 * t + 1][2], p13 = s[2 * t + 1][3];
            float h00 = h_round(p00), h01 = h_round(p01);
            float h02 = h_round(p02), h03 = h_round(p03);
            float h10 = h_round(p10), h11 = h_round(p11);
            float h12 = h_round(p12), h13 = h_round(p13);
            uint32_t ph[4], pl[4];
            ph[0] = packh(h00, h01); ph[1] = packh(h02, h03);
            ph[2] = packh(h10, h11); ph[3] = packh(h12, h13);
            pl[0] = packh(p00 - h00, p01 - h01);
            pl[1] = packh(p02 - h02, p03 - h03);
            pl[2] = packh(p10 - h10, p11 - h11);
            pl[3] = packh(p12 - h12, p13 - h13);
            #pragma unroll
            for (int jp = 0; jp < 4; jp++) {
                uint32_t vb[4];
                int row = t * 16 + (lane & 15);
                int col = jp * 16 + ((lane >> 4) << 3);
                ldsm_x4t(vb, sV + (uint32_t)(row * TSTR + col) * 2);
                mma_h(o[2 * jp],     ph, vb);
                mma_h(o[2 * jp],     pl, vb);
                mma_h(o[2 * jp + 1], ph, vb + 2);
                mma_h(o[2 * jp + 1], pl, vb + 2);
            }
        }

        if (kt + 1 < SEQ / 64) cp_wait0();
        __syncthreads();
    }

    // ---- finalize + split-bf16 store ----
    const float il0 = 1.0f / l0, il1 = 1.0f / l1;
    const long base = (long)(b * SEQ + qt * 128 + warp * 16 + (lane >> 2)) * DIM + h * HD;
    #pragma unroll
    for (int j = 0; j < 8; j++) {
        const int col = j * 8 + 2 * (lane & 3);
        float v0 = o[j][0] * il0, v1 = o[j][1] * il0;
        float v2 = o[j][2] * il1, v3 = o[j][3] * il1;
        __nv_bfloat162 b01 = __floats2bfloat162_rn(v0, v1);
        __nv_bfloat162 b23 = __floats2bfloat162_rn(v2, v3);
        *reinterpret_cast<uint32_t*>(&Oh_g[base + col]) =
            *reinterpret_cast<uint32_t*>(&b01);
        *reinterpret_cast<uint32_t*>(&Oh_g[base + 8L * DIM + col]) =
            *reinterpret_cast<uint32_t*>(&b23);
        __nv_bfloat162 l01 = __floats2bfloat162_rn(v0 - __bfloat162float(b01.x),
                                                   v1 - __bfloat162float(b01.y));
        __nv_bfloat162 l23 = __floats2bfloat162_rn(v2 - __bfloat162float(b23.x),
                                                   v3 - __bfloat162float(b23.y));
        *reinterpret_cast<uint32_t*>(&Ol_g[base + col]) =
            *reinterpret_cast<uint32_t*>(&l01);
        *reinterpret_cast<uint32_t*>(&Ol_g[base + 8L * DIM + col]) =
            *reinterpret_cast<uint32_t*>(&l23);
    }
}

// ============================================================================
// kernel_launch
// ============================================================================
extern "C" void kernel_launch(void* const* d_in, const int* in_sizes, int n_in,
                              void* d_out, int out_size)
{
    const float* x  = (const float*)d_in[0];
    const float* Wq = (const float*)d_in[1];
    const float* Wk = (const float*)d_in[2];
    const float* Wv = (const float*)d_in[3];
    const float* Wo = (const float*)d_in[4];
    float* out = (float*)d_out;

    void *pxh, *pxl, *pqh, *pql, *pkh, *pkl, *pvh, *pvl, *poh, *pol;
    void *pQh, *pQl, *pKh, *pVh, *pOh, *pOl;
    cudaGetSymbolAddress(&pxh, g_xh);  cudaGetSymbolAddress(&pxl, g_xl);
    cudaGetSymbolAddress(&pqh, g_Wqh); cudaGetSymbolAddress(&pql, g_Wql);
    cudaGetSymbolAddress(&pkh, g_Wkh); cudaGetSymbolAddress(&pkl, g_Wkl);
    cudaGetSymbolAddress(&pvh, g_Wvh); cudaGetSymbolAddress(&pvl, g_Wvl);
    cudaGetSymbolAddress(&poh, g_Woh); cudaGetSymbolAddress(&pol, g_Wol);
    cudaGetSymbolAddress(&pQh, g_Qh);  cudaGetSymbolAddress(&pQl, g_Ql);
    cudaGetSymbolAddress(&pKh, g_Kh);  cudaGetSymbolAddress(&pVh, g_Vh);
    cudaGetSymbolAddress(&pOh, g_Oh);  cudaGetSymbolAddress(&pOl, g_Ol);

    cudaFuncSetAttribute((const void*)gemm_split<0>,
                         cudaFuncAttributeMaxDynamicSharedMemorySize, G_SMEM);
    cudaFuncSetAttribute((const void*)gemm_split<2>,
                         cudaFuncAttributeMaxDynamicSharedMemorySize, G_SMEM);
    cudaFuncSetAttribute((const void*)gemm_split<3>,
                         cudaFuncAttributeMaxDynamicSharedMemorySize, G_SMEM);
    cudaFuncSetAttribute((const void*)attn_fp16,
                         cudaFuncAttributeMaxDynamicSharedMemorySize, ATTN_SMEM);

    // pre-split inputs to bf16 hi/lo
    split_bf16<<<ROWS * DIM / 1024, 256>>>((const float4*)x,
        (__nv_bfloat16*)pxh, (__nv_bfloat16*)pxl, ROWS * DIM / 4);
    split_bf16<<<DIM * DIM / 1024, 256>>>((const float4*)Wq,
        (__nv_bfloat16*)pqh, (__nv_bfloat16*)pql, DIM * DIM / 4);
    split_bf16<<<DIM * KVDIM / 1024, 256>>>((const float4*)Wk,
        (__nv_bfloat16*)pkh, (__nv_bfloat16*)pkl, DIM * KVDIM / 4);
    split_bf16<<<DIM * KVDIM / 1024, 256>>>((const float4*)Wv,
        (__nv_bfloat16*)pvh, (__nv_bfloat16*)pvl, DIM * KVDIM / 4);
    split_bf16<<<DIM * DIM / 1024, 256>>>((const float4*)Wo,
        (__nv_bfloat16*)poh, (__nv_bfloat16*)pol, DIM * DIM / 4);

    // Q = 0.125 * x @ Wq  -> fp16 hi/lo
    gemm_split<2><<<dim3(DIM / 128, ROWS / 128), 256, G_SMEM>>>(
        DIM, DIM, (__nv_bfloat16*)pxh, (__nv_bfloat16*)pxl,
        (__nv_bfloat16*)pqh, (__nv_bfloat16*)pql, pQh, pQl, 0.125f);
    // K = x @ Wk -> fp16
    gemm_split<3><<<dim3(KVDIM / 128, ROWS / 128), 256, G_SMEM>>>(
        KVDIM, DIM, (__nv_bfloat16*)pxh, (__nv_bfloat16*)pxl,
        (__nv_bfloat16*)pkh, (__nv_bfloat16*)pkl, pKh, nullptr, 1.0f);
    // V = x @ Wv -> fp16
    gemm_split<3><<<dim3(KVDIM / 128, ROWS / 128), 256, G_SMEM>>>(
        KVDIM, DIM, (__nv_bfloat16*)pxh, (__nv_bfloat16*)pxl,
        (__nv_bfloat16*)pvh, (__nv_bfloat16*)pvl, pVh, nullptr, 1.0f);
    // attention -> bf16 hi/lo
    attn_fp16<<<dim3(SEQ / 128, NHEADS, BATCH), 256, ATTN_SMEM>>>(
        (const __half*)pQh, (const __half*)pQl,
        (const __half*)pKh, (const __half*)pVh,
        (__nv_bfloat16*)pOh, (__nv_bfloat16*)pOl);
    // out = O @ Wo -> fp32
    gemm_split<0><<<dim3(DIM / 128, ROWS / 128), 256, G_SMEM>>>(
        DIM, DIM, (__nv_bfloat16*)pOh, (__nv_bfloat16*)pOl,
        (__nv_bfloat16*)poh, (__nv_bfloat16*)pol, out, nullptr, 1.0f);
}

// round 4
// speedup vs baseline: 4.2500x; 1.1785x over previous
#include <cuda_runtime.h>
#include <cuda_bf16.h>
#include <cuda_fp16.h>
#include <cstdint>

#define DIM      2048
#define KVDIM    512
#define SEQ      2048
#define BATCH    2
#define NHEADS   32
#define HD       64
#define ROWS     (BATCH * SEQ)   // 4096

// -------- static scratch (no allocations allowed) --------
__device__ __half g_xh[ROWS * DIM],  g_xl[ROWS * DIM];     // x split fp16
__device__ __half g_Wq[DIM * DIM];                         // weights fp16 single
__device__ __half g_Wk[DIM * KVDIM];
__device__ __half g_Wv[DIM * KVDIM];
__device__ __half g_Wo[DIM * DIM];
__device__ __half g_Qh[ROWS * DIM],  g_Ql[ROWS * DIM];     // Q pre-scaled fp16 split
__device__ __half g_Kh[ROWS * KVDIM], g_Vh[ROWS * KVDIM];  // K,V fp16
__device__ __half g_Oh[ROWS * DIM],  g_Ol[ROWS * DIM];     // attn out fp16 split

// ============================================================================
// helpers
// ============================================================================
__device__ __forceinline__ uint32_t smem_u32(const void* p) {
    return (uint32_t)__cvta_generic_to_shared(p);
}
__device__ __forceinline__ void ldsm_x4(uint32_t* r, uint32_t addr) {
    asm volatile("ldmatrix.sync.aligned.m8n8.x4.shared.b16 {%0,%1,%2,%3}, [%4];"
                 : "=r"(r[0]), "=r"(r[1]), "=r"(r[2]), "=r"(r[3]) : "r"(addr));
}
__device__ __forceinline__ void ldsm_x4t(uint32_t* r, uint32_t addr) {
    asm volatile("ldmatrix.sync.aligned.m8n8.x4.trans.shared.b16 {%0,%1,%2,%3}, [%4];"
                 : "=r"(r[0]), "=r"(r[1]), "=r"(r[2]), "=r"(r[3]) : "r"(addr));
}
__device__ __forceinline__ void mma_h(float* c, const uint32_t* a, const uint32_t* b) {
    asm volatile(
        "mma.sync.aligned.m16n8k16.row.col.f32.f16.f16.f32 "
        "{%0,%1,%2,%3}, {%4,%5,%6,%7}, {%8,%9}, {%0,%1,%2,%3};"
        : "+f"(c[0]), "+f"(c[1]), "+f"(c[2]), "+f"(c[3])
        : "r"(a[0]), "r"(a[1]), "r"(a[2]), "r"(a[3]), "r"(b[0]), "r"(b[1]));
}
__device__ __forceinline__ void cp16(uint32_t dst, const void* src) {
    asm volatile("cp.async.cg.shared.global [%0], [%1], 16;" :: "r"(dst), "l"(src));
}
__device__ __forceinline__ void cp_commit() { asm volatile("cp.async.commit_group;"); }
__device__ __forceinline__ void cp_wait0()  { asm volatile("cp.async.wait_group 0;"); }

__device__ __forceinline__ uint32_t packh(float a, float b) {
    __half2 t = __floats2half2_rn(a, b);
    return *reinterpret_cast<uint32_t*>(&t);
}
__device__ __forceinline__ float h_round(float x) {
    return __half2float(__float2half_rn(x));
}

// ============================================================================
// pre-pass kernels: x -> fp16 hi/lo ; W -> fp16
// ============================================================================
__global__ __launch_bounds__(256) void split_fp16(
    const float4* __restrict__ src, __half* __restrict__ hi,
    __half* __restrict__ lo, int n4)
{
    int i = blockIdx.x * 256 + threadIdx.x;
    if (i >= n4) return;
    float4 v = src[i];
    float h0 = h_round(v.x), h1 = h_round(v.y);
    float h2 = h_round(v.z), h3 = h_round(v.w);
    uint2 hh, ll;
    hh.x = packh(h0, h1);          hh.y = packh(h2, h3);
    ll.x = packh(v.x - h0, v.y - h1); ll.y = packh(v.z - h2, v.w - h3);
    *reinterpret_cast<uint2*>(hi + (long)i * 4) = hh;
    *reinterpret_cast<uint2*>(lo + (long)i * 4) = ll;
}

__global__ __launch_bounds__(256) void conv_fp16(
    const float4* __restrict__ src, __half* __restrict__ dst, int n4)
{
    int i = blockIdx.x * 256 + threadIdx.x;
    if (i >= n4) return;
    float4 v = src[i];
    uint2 hh;
    hh.x = packh(v.x, v.y);
    hh.y = packh(v.z, v.w);
    *reinterpret_cast<uint2*>(dst + (long)i * 4) = hh;
}

// ============================================================================
// fp16 2-product GEMM: C = (Ah + Al) * B, cp.async double buffered.
// Block tile 128x128, BK=32, 256 threads (8 warps 2x4), warp tile 64x32.
// EPI: 0 = fp32 out ; 2 = fp16 split (out0=hi,out1=lo, scaled) ; 3 = fp16
// ============================================================================
#define GASTR 40
#define GBSTR 136
#define G_ABYTES (128 * GASTR * 2)                 // 10240
#define G_BBYTES (32 * GBSTR * 2)                  //  8704
#define G_STAGE  (2 * G_ABYTES + G_BBYTES)         // 29184
#define G_SMEM   (2 * G_STAGE)                     // 58368

template<int EPI>
__global__ __launch_bounds__(256) void gemm_fp16(
    int N, int K,
    const __half* __restrict__ Ah, const __half* __restrict__ Al,
    const __half* __restrict__ B,
    void* __restrict__ out0, void* __restrict__ out1, float scale)
{
    extern __shared__ __align__(16) char gsm[];
    const uint32_t sbase = smem_u32(gsm);

    const int tid  = threadIdx.x;
    const int lane = tid & 31;
    const int warp = tid >> 5;
    const int wm   = warp >> 2;
    const int wn   = warp & 3;
    const long M0  = (long)blockIdx.y * 128;
    const long N0  = (long)blockIdx.x * 128;

    float c[4][4][4];
    #pragma unroll
    for (int i = 0; i < 4; i++)
        #pragma unroll
        for (int j = 0; j < 4; j++)
            #pragma unroll
            for (int e = 0; e < 4; e++) c[i][j][e] = 0.0f;

    auto loadStage = [&](int st, int k0) {
        uint32_t sA  = sbase + st * G_STAGE;
        uint32_t sAl = sA + G_ABYTES;
        uint32_t sB  = sA + 2 * G_ABYTES;
        #pragma unroll
        for (int i = 0; i < 2; i++) {
            int ci = tid + i * 256;
            int row = ci >> 2, c8 = ci & 3;
            uint32_t so = (uint32_t)(row * GASTR + c8 * 8) * 2;
            long go = (M0 + row) * (long)K + k0 + c8 * 8;
            cp16(sA + so, Ah + go);
            cp16(sAl + so, Al + go);
        }
        #pragma unroll
        for (int i = 0; i < 2; i++) {
            int ci = tid + i * 256;
            int row = ci >> 4, c8 = ci & 15;
            uint32_t so = (uint32_t)(row * GBSTR + c8 * 8) * 2;
            long go = (long)(k0 + row) * N + N0 + c8 * 8;
            cp16(sB + so, B + go);
        }
    };

    const int nk = K / 32;
    loadStage(0, 0);
    cp_commit();

    for (int kt = 0; kt < nk; kt++) {
        cp_wait0();
        __syncthreads();
        if (kt + 1 < nk) loadStage((kt + 1) & 1, (kt + 1) * 32);
        cp_commit();

        uint32_t sA  = sbase + (kt & 1) * G_STAGE;
        uint32_t sAl = sA + G_ABYTES;
        uint32_t sB  = sA + 2 * G_ABYTES;

        #pragma unroll
        for (int kk = 0; kk < 32; kk += 16) {
            uint32_t ah[4][4], al[4][4], bb[2][4];
            #pragma unroll
            for (int i = 0; i < 4; i++) {
                int row = wm * 64 + i * 16 + (lane & 15);
                int col = kk + (lane >> 4) * 8;
                uint32_t off = (uint32_t)(row * GASTR + col) * 2;
                ldsm_x4(ah[i], sA + off);
                ldsm_x4(al[i], sAl + off);
            }
            #pragma unroll
            for (int jp = 0; jp < 2; jp++) {
                int row = kk + (lane & 15);
                int col = wn * 32 + jp * 16 + ((lane >> 4) << 3);
                uint32_t off = (uint32_t)(row * GBSTR + col) * 2;
                ldsm_x4t(bb[jp], sB + off);
            }
            #pragma unroll
            for (int i = 0; i < 4; i++)
                #pragma unroll
                for (int jp = 0; jp < 2; jp++) {
                    mma_h(c[i][2 * jp],     ah[i], bb[jp]);
                    mma_h(c[i][2 * jp],     al[i], bb[jp]);
                    mma_h(c[i][2 * jp + 1], ah[i], bb[jp] + 2);
                    mma_h(c[i][2 * jp + 1], al[i], bb[jp] + 2);
                }
        }
    }

    // epilogue
    #pragma unroll
    for (int i = 0; i < 4; i++) {
        long r0 = M0 + wm * 64 + i * 16 + (lane >> 2);
        #pragma unroll
        for (int j = 0; j < 4; j++) {
            long cc = N0 + wn * 32 + j * 8 + 2 * (lane & 3);
            float v0 = c[i][j][0] * scale, v1 = c[i][j][1] * scale;
            float v2 = c[i][j][2] * scale, v3 = c[i][j][3] * scale;
            if (EPI == 0) {
                float* C = (float*)out0;
                *reinterpret_cast<float2*>(&C[r0 * N + cc])       = make_float2(v0, v1);
                *reinterpret_cast<float2*>(&C[(r0 + 8) * N + cc]) = make_float2(v2, v3);
            } else if (EPI == 2) {
                __half* Ch = (__half*)out0;
                __half* Cl = (__half*)out1;
                float h0 = h_round(v0), h1 = h_round(v1);
                float h2 = h_round(v2), h3 = h_round(v3);
                *reinterpret_cast<uint32_t*>(&Ch[r0 * N + cc])       = packh(h0, h1);
                *reinterpret_cast<uint32_t*>(&Ch[(r0 + 8) * N + cc]) = packh(h2, h3);
                *reinterpret_cast<uint32_t*>(&Cl[r0 * N + cc])       = packh(v0 - h0, v1 - h1);
                *reinterpret_cast<uint32_t*>(&Cl[(r0 + 8) * N + cc]) = packh(v2 - h2, v3 - h3);
            } else { // EPI == 3
                __half* Ch = (__half*)out0;
                *reinterpret_cast<uint32_t*>(&Ch[r0 * N + cc])       = packh(v0, v1);
                *reinterpret_cast<uint32_t*>(&Ch[(r0 + 8) * N + cc]) = packh(v2, v3);
            }
        }
    }
}

// ============================================================================
// fp16 flash attention (unchanged math; output now fp16 hi/lo).
// Block 256 thr (8 warps), 128 q-rows of one (b,h); warp owns 16 rows.
// ============================================================================
#define TSTR 72
#define Q_BYTES  (128 * TSTR * 2)
#define KV_BYTES (64 * TSTR * 2)
#define A_STAGE  (2 * KV_BYTES)
#define ATTN_SMEM (2 * Q_BYTES + 2 * A_STAGE)   // 73728

__global__ __launch_bounds__(256) void attn_fp16(
    const __half* __restrict__ Qh_g, const __half* __restrict__ Ql_g,
    const __half* __restrict__ K_g,  const __half* __restrict__ V_g,
    __half* __restrict__ Oh_g, __half* __restrict__ Ol_g)
{
    extern __shared__ __align__(16) char smp[];
    const uint32_t sb  = smem_u32(smp);
    const uint32_t sQh = sb;
    const uint32_t sQl = sb + Q_BYTES;
    const uint32_t sKV = sb + 2 * Q_BYTES;

    const int tid  = threadIdx.x;
    const int lane = tid & 31;
    const int warp = tid >> 5;
    const int qt = blockIdx.x, h = blockIdx.y, b = blockIdx.z;
    const int kvh = h >> 2;

    auto loadKV = [&](int st, int kt) {
        uint32_t sK = sKV + st * A_STAGE;
        uint32_t sV = sK + KV_BYTES;
        #pragma unroll
        for (int i = 0; i < 2; i++) {
            int ci = tid + i * 256;
            int row = ci >> 3, c8 = ci & 7;
            uint32_t so = (uint32_t)(row * TSTR + c8 * 8) * 2;
            long go = (long)(b * SEQ + kt * 64 + row) * KVDIM + kvh * HD + c8 * 8;
            cp16(sK + so, K_g + go);
            cp16(sV + so, V_g + go);
        }
    };

    #pragma unroll
    for (int i = 0; i < 4; i++) {
        int ci = tid + i * 256;
        int row = ci >> 3, c8 = ci & 7;
        uint32_t so = (uint32_t)(row * TSTR + c8 * 8) * 2;
        long go = (long)(b * SEQ + qt * 128 + row) * DIM + h * HD + c8 * 8;
        cp16(sQh + so, Qh_g + go);
        cp16(sQl + so, Ql_g + go);
    }
    loadKV(0, 0);
    cp_commit();
    cp_wait0();
    __syncthreads();

    uint32_t qh[4][4], ql[4][4];
    #pragma unroll
    for (int t = 0; t < 4; t++) {
        int row = warp * 16 + (lane & 15);
        int col = t * 16 + (lane >> 4) * 8;
        uint32_t off = (uint32_t)(row * TSTR + col) * 2;
        ldsm_x4(qh[t], sQh + off);
        ldsm_x4(ql[t], sQl + off);
    }

    float o[8][4];
    #pragma unroll
    for (int j = 0; j < 8; j++)
        #pragma unroll
        for (int e = 0; e < 4; e++) o[j][e] = 0.0f;
    float m0v = -1e30f, m1v = -1e30f, l0 = 0.0f, l1 = 0.0f;

    for (int kt = 0; kt < SEQ / 64; kt++) {
        const int cur = kt & 1;
        if (kt + 1 < SEQ / 64) { loadKV(cur ^ 1, kt + 1); }
        cp_commit();

        const uint32_t sK = sKV + cur * A_STAGE;
        const uint32_t sV = sK + KV_BYTES;

        float s[8][4];
        #pragma unroll
        for (int j = 0; j < 8; j++)
            #pragma unroll
            for (int e = 0; e < 4; e++) s[j][e] = 0.0f;

        const int l7 = lane & 7, g4 = lane >> 3;
        #pragma unroll
        for (int t = 0; t < 4; t++) {
            #pragma unroll
            for (int jp = 0; jp < 4; jp++) {
                uint32_t kb[4];
                int row = jp * 16 + ((g4 >> 1) << 3) + l7;
                int col = t * 16 + ((g4 & 1) << 3);
                ldsm_x4(kb, sK + (uint32_t)(row * TSTR + col) * 2);
                mma_h(s[2 * jp],     qh[t], kb);
                mma_h(s[2 * jp],     ql[t], kb);
                mma_h(s[2 * jp + 1], qh[t], kb + 2);
                mma_h(s[2 * jp + 1], ql[t], kb + 2);
            }
        }

        float tm0 = -1e30f, tm1 = -1e30f;
        #pragma unroll
        for (int j = 0; j < 8; j++) {
            tm0 = fmaxf(tm0, fmaxf(s[j][0], s[j][1]));
            tm1 = fmaxf(tm1, fmaxf(s[j][2], s[j][3]));
        }
        #pragma unroll
        for (int off = 1; off <= 2; off <<= 1) {
            tm0 = fmaxf(tm0, __shfl_xor_sync(0xffffffffu, tm0, off));
            tm1 = fmaxf(tm1, __shfl_xor_sync(0xffffffffu, tm1, off));
        }
        const float mn0 = fmaxf(m0v, tm0), mn1 = fmaxf(m1v, tm1);
        const float a0 = __expf(m0v - mn0), a1 = __expf(m1v - mn1);
        m0v = mn0; m1v = mn1;

        float sum0 = 0.0f, sum1 = 0.0f;
        #pragma unroll
        for (int j = 0; j < 8; j++) {
            s[j][0] = __expf(s[j][0] - mn0);
            s[j][1] = __expf(s[j][1] - mn0);
            s[j][2] = __expf(s[j][2] - mn1);
            s[j][3] = __expf(s[j][3] - mn1);
            sum0 += s[j][0] + s[j][1];
            sum1 += s[j][2] + s[j][3];
        }
        #pragma unroll
        for (int off = 1; off <= 2; off <<= 1) {
            sum0 += __shfl_xor_sync(0xffffffffu, sum0, off);
            sum1 += __shfl_xor_sync(0xffffffffu, sum1, off);
        }
        l0 = l0 * a0 + sum0;
        l1 = l1 * a1 + sum1;
        #pragma unroll
        for (int j = 0; j < 8; j++) {
            o[j][0] *= a0; o[j][1] *= a0;
            o[j][2] *= a1; o[j][3] *= a1;
        }

        #pragma unroll
        for (int t = 0; t < 4; t++) {
            float p00 = s[2 * t][0],     p01 = s[2 * t][1];
            float p02 = s[2 * t][2],     p03 = s[2 * t][3];
            float p10 = s[2 * t + 1][0], p11 = s[2 * t + 1][1];
            float p12 = s[2 * t + 1][2], p13 = s[2 * t + 1][3];
            float h00 = h_round(p00), h01 = h_round(p01);
            float h02 = h_round(p02), h03 = h_round(p03);
            float h10 = h_round(p10), h11 = h_round(p11);
            float h12 = h_round(p12), h13 = h_round(p13);
            uint32_t ph[4], pl[4];
            ph[0] = packh(h00, h01); ph[1] = packh(h02, h03);
            ph[2] = packh(h10, h11); ph[3] = packh(h12, h13);
            pl[0] = packh(p00 - h00, p01 - h01);
            pl[1] = packh(p02 - h02, p03 - h03);
            pl[2] = packh(p10 - h10, p11 - h11);
            pl[3] = packh(p12 - h12, p13 - h13);
            #pragma unroll
            for (int jp = 0; jp < 4; jp++) {
                uint32_t vb[4];
                int row = t * 16 + (lane & 15);
                int col = jp * 16 + ((lane >> 4) << 3);
                ldsm_x4t(vb, sV + (uint32_t)(row * TSTR + col) * 2);
                mma_h(o[2 * jp],     ph, vb);
                mma_h(o[2 * jp],     pl, vb);
                mma_h(o[2 * jp + 1], ph, vb + 2);
                mma_h(o[2 * jp + 1], pl, vb + 2);
            }
        }

        if (kt + 1 < SEQ / 64) cp_wait0();
        __syncthreads();
    }

    // ---- finalize + fp16 split store ----
    const float il0 = 1.0f / l0, il1 = 1.0f / l1;
    const long base = (long)(b * SEQ + qt * 128 + warp * 16 + (lane >> 2)) * DIM + h * HD;
    #pragma unroll
    for (int j = 0; j < 8; j++) {
        const int col = j * 8 + 2 * (lane & 3);
        float v0 = o[j][0] * il0, v1 = o[j][1] * il0;
        float v2 = o[j][2] * il1, v3 = o[j][3] * il1;
        float h0 = h_round(v0), h1 = h_round(v1);
        float h2 = h_round(v2), h3 = h_round(v3);
        *reinterpret_cast<uint32_t*>(&Oh_g[base + col])            = packh(h0, h1);
        *reinterpret_cast<uint32_t*>(&Oh_g[base + 8L * DIM + col]) = packh(h2, h3);
        *reinterpret_cast<uint32_t*>(&Ol_g[base + col])            = packh(v0 - h0, v1 - h1);
        *reinterpret_cast<uint32_t*>(&Ol_g[base + 8L * DIM + col]) = packh(v2 - h2, v3 - h3);
    }
}

// ============================================================================
// kernel_launch
// ============================================================================
extern "C" void kernel_launch(void* const* d_in, const int* in_sizes, int n_in,
                              void* d_out, int out_size)
{
    const float* x  = (const float*)d_in[0];
    const float* Wq = (const float*)d_in[1];
    const float* Wk = (const float*)d_in[2];
    const float* Wv = (const float*)d_in[3];
    const float* Wo = (const float*)d_in[4];
    float* out = (float*)d_out;

    void *pxh, *pxl, *pwq, *pwk, *pwv, *pwo;
    void *pQh, *pQl, *pKh, *pVh, *pOh, *pOl;
    cudaGetSymbolAddress(&pxh, g_xh);  cudaGetSymbolAddress(&pxl, g_xl);
    cudaGetSymbolAddress(&pwq, g_Wq);  cudaGetSymbolAddress(&pwk, g_Wk);
    cudaGetSymbolAddress(&pwv, g_Wv);  cudaGetSymbolAddress(&pwo, g_Wo);
    cudaGetSymbolAddress(&pQh, g_Qh);  cudaGetSymbolAddress(&pQl, g_Ql);
    cudaGetSymbolAddress(&pKh, g_Kh);  cudaGetSymbolAddress(&pVh, g_Vh);
    cudaGetSymbolAddress(&pOh, g_Oh);  cudaGetSymbolAddress(&pOl, g_Ol);

    cudaFuncSetAttribute((const void*)gemm_fp16<0>,
                         cudaFuncAttributeMaxDynamicSharedMemorySize, G_SMEM);
    cudaFuncSetAttribute((const void*)gemm_fp16<2>,
                         cudaFuncAttributeMaxDynamicSharedMemorySize, G_SMEM);
    cudaFuncSetAttribute((const void*)gemm_fp16<3>,
                         cudaFuncAttributeMaxDynamicSharedMemorySize, G_SMEM);
    cudaFuncSetAttribute((const void*)attn_fp16,
                         cudaFuncAttributeMaxDynamicSharedMemorySize, ATTN_SMEM);

    // pre-pass: split x, convert weights
    split_fp16<<<ROWS * DIM / 1024, 256>>>((const float4*)x,
        (__half*)pxh, (__half*)pxl, ROWS * DIM / 4);
    conv_fp16<<<DIM * DIM / 1024, 256>>>((const float4*)Wq, (__half*)pwq, DIM * DIM / 4);
    conv_fp16<<<DIM * KVDIM / 1024, 256>>>((const float4*)Wk, (__half*)pwk, DIM * KVDIM / 4);
    conv_fp16<<<DIM * KVDIM / 1024, 256>>>((const float4*)Wv, (__half*)pwv, DIM * KVDIM / 4);
    conv_fp16<<<DIM * DIM / 1024, 256>>>((const float4*)Wo, (__half*)pwo, DIM * DIM / 4);

    // Q = 0.125 * x @ Wq -> fp16 hi/lo
    gemm_fp16<2><<<dim3(DIM / 128, ROWS / 128), 256, G_SMEM>>>(
        DIM, DIM, (__half*)pxh, (__half*)pxl, (__half*)pwq, pQh, pQl, 0.125f);
    // K = x @ Wk -> fp16
    gemm_fp16<3><<<dim3(KVDIM / 128, ROWS / 128), 256, G_SMEM>>>(
        KVDIM, DIM, (__half*)pxh, (__half*)pxl, (__half*)pwk, pKh, nullptr, 1.0f);
    // V = x @ Wv -> fp16
    gemm_fp16<3><<<dim3(KVDIM / 128, ROWS / 128), 256, G_SMEM>>>(
        KVDIM, DIM, (__half*)pxh, (__half*)pxl, (__half*)pwv, pVh, nullptr, 1.0f);
    // attention -> fp16 hi/lo
    attn_fp16<<<dim3(SEQ / 128, NHEADS, BATCH), 256, ATTN_SMEM>>>(
        (const __half*)pQh, (const __half*)pQl,
        (const __half*)pKh, (const __half*)pVh,
        (__half*)pOh, (__half*)pOl);
    // out = O @ Wo -> fp32
    gemm_fp16<0><<<dim3(DIM / 128, ROWS / 128), 256, G_SMEM>>>(
        DIM, DIM, (__half*)pOh, (__half*)pOl, (__half*)pwo, out, nullptr, 1.0f);
}

// round 6
// speedup vs baseline: 6.0090x; 1.4139x over previous
#include <cuda_runtime.h>
#include <cuda_fp16.h>
#include <cstdint>

#define DIM      2048
#define KVDIM    512
#define QKVN     (DIM + 2 * KVDIM)   // 3072
#define SEQ      2048
#define BATCH    2
#define NHEADS   32
#define HD       64
#define ROWS     (BATCH * SEQ)   // 4096

// -------- static scratch (no allocations allowed) --------
__device__ __half g_xh[ROWS * DIM],  g_xl[ROWS * DIM];   // x split fp16 (exact)
__device__ __half g_Wqkv[DIM * QKVN];                    // [2048][3072] fp16
__device__ __half g_Wo[DIM * DIM];                       // [2048][2048] fp16
__device__ __half g_Q[ROWS * DIM];                       // pre-scaled fp16
__device__ __half g_K[ROWS * KVDIM], g_V[ROWS * KVDIM];  // fp16
__device__ __half g_Oh[ROWS * DIM],  g_Ol[ROWS * DIM];   // attn out fp16 split

// ============================================================================
// helpers
// ============================================================================
__device__ __forceinline__ uint32_t smem_u32(const void* p) {
    return (uint32_t)__cvta_generic_to_shared(p);
}
__device__ __forceinline__ void ldsm_x4(uint32_t* r, uint32_t addr) {
    asm volatile("ldmatrix.sync.aligned.m8n8.x4.shared.b16 {%0,%1,%2,%3}, [%4];"
                 : "=r"(r[0]), "=r"(r[1]), "=r"(r[2]), "=r"(r[3]) : "r"(addr));
}
__device__ __forceinline__ void ldsm_x4t(uint32_t* r, uint32_t addr) {
    asm volatile("ldmatrix.sync.aligned.m8n8.x4.trans.shared.b16 {%0,%1,%2,%3}, [%4];"
                 : "=r"(r[0]), "=r"(r[1]), "=r"(r[2]), "=r"(r[3]) : "r"(addr));
}
__device__ __forceinline__ void mma_h(float* c, const uint32_t* a, const uint32_t* b) {
    asm volatile(
        "mma.sync.aligned.m16n8k16.row.col.f32.f16.f16.f32 "
        "{%0,%1,%2,%3}, {%4,%5,%6,%7}, {%8,%9}, {%0,%1,%2,%3};"
        : "+f"(c[0]), "+f"(c[1]), "+f"(c[2]), "+f"(c[3])
        : "r"(a[0]), "r"(a[1]), "r"(a[2]), "r"(a[3]), "r"(b[0]), "r"(b[1]));
}
__device__ __forceinline__ void cp16(uint32_t dst, const void* src) {
    asm volatile("cp.async.cg.shared.global [%0], [%1], 16;" :: "r"(dst), "l"(src));
}
__device__ __forceinline__ void cp_commit() { asm volatile("cp.async.commit_group;"); }
__device__ __forceinline__ void cp_wait0()  { asm volatile("cp.async.wait_group 0;"); }
__device__ __forceinline__ void cp_wait1()  { asm volatile("cp.async.wait_group 1;"); }

__device__ __forceinline__ uint32_t packh(float a, float b) {
    __half2 t = __floats2half2_rn(a, b);
    return *reinterpret_cast<uint32_t*>(&t);
}
__device__ __forceinline__ float h_round(float x) {
    return __half2float(__float2half_rn(x));
}

#define SW64(off)  ((off) ^ (((off) >> 3) & 0x30))

// ============================================================================
// pre-pass kernels
// ============================================================================
__global__ __launch_bounds__(256) void split_fp16(
    const float4* __restrict__ src, __half* __restrict__ hi,
    __half* __restrict__ lo, int n4)
{
    int i = blockIdx.x * 256 + threadIdx.x;
    if (i >= n4) return;
    float4 v = src[i];
    float h0 = h_round(v.x), h1 = h_round(v.y);
    float h2 = h_round(v.z), h3 = h_round(v.w);
    uint2 hh, ll;
    hh.x = packh(h0, h1);             hh.y = packh(h2, h3);
    ll.x = packh(v.x - h0, v.y - h1); ll.y = packh(v.z - h2, v.w - h3);
    *reinterpret_cast<uint2*>(hi + (long)i * 4) = hh;
    *reinterpret_cast<uint2*>(lo + (long)i * 4) = ll;
}

// fp32 [K][N] -> fp16 written into dst[row * dstride + coloff + col]
__global__ __launch_bounds__(256) void conv_fp16_strided(
    const float4* __restrict__ src, __half* __restrict__ dst,
    int N4, int dstride, int coloff, int n4)
{
    int i = blockIdx.x * 256 + threadIdx.x;
    if (i >= n4) return;
    float4 v = src[i];
    int row = i / N4, c4 = i % N4;
    uint2 hh;
    hh.x = packh(v.x, v.y);
    hh.y = packh(v.z, v.w);
    *reinterpret_cast<uint2*>(dst + (long)row * dstride + coloff + c4 * 4) = hh;
}

// ============================================================================
// fp16 2-product GEMM: C = (Ah + Al) * B.  K = 2048 fixed.
// Block tile 128x128, BK=32, 256 threads (8 warps 2x4), warp tile 64x32.
// A smem: 128 rows x 32 halfs, SW64 swizzle (8 KB each for hi/lo).
// B smem: 32 rows x 136 halfs padded (8704 B).
// 3-stage cp.async pipeline, wait_group 1.
// EPI: 0 = fp32 out0 ; 1 = fused QKV (q scaled fp16 / k fp16 / v fp16)
// ============================================================================
#define GK      2048
#define G_NK    (GK / 32)          // 64
#define G_AB    8192
#define G_BB    8704
#define G_ST    (2 * G_AB + G_BB)  // 25088
#define G_SMEM  (3 * G_ST)         // 75264
#define GBSTR   136

template<int EPI>
__global__ __launch_bounds__(256) void gemm_fp16(
    int Bstride,
    const __half* __restrict__ Ah, const __half* __restrict__ Al,
    const __half* __restrict__ B,
    void* __restrict__ out0, void* __restrict__ out1, void* __restrict__ out2)
{
    extern __shared__ __align__(16) char gsm[];
    const uint32_t sbase = smem_u32(gsm);

    const int tid  = threadIdx.x;
    const int lane = tid & 31;
    const int warp = tid >> 5;
    const int wm   = warp >> 2;
    const int wn   = warp & 3;
    const long M0  = (long)blockIdx.y * 128;
    const long N0  = (long)blockIdx.x * 128;

    float c[4][4][4];
    #pragma unroll
    for (int i = 0; i < 4; i++)
        #pragma unroll
        for (int j = 0; j < 4; j++)
            #pragma unroll
            for (int e = 0; e < 4; e++) c[i][j][e] = 0.0f;

    auto loadStage = [&](int st, int k0) {
        uint32_t sA  = sbase + st * G_ST;
        uint32_t sAl = sA + G_AB;
        uint32_t sB  = sA + 2 * G_AB;
        #pragma unroll
        for (int i = 0; i < 2; i++) {
            int ci = tid + i * 256;
            int row = ci >> 2, ch = ci & 3;
            uint32_t so = SW64((uint32_t)(row * 64 + ch * 16));
            long go = (M0 + row) * (long)GK + k0 + ch * 8;
            cp16(sA + so, Ah + go);
            cp16(sAl + so, Al + go);
        }
        #pragma unroll
        for (int i = 0; i < 2; i++) {
            int ci = tid + i * 256;
            int row = ci >> 4, c8 = ci & 15;
            uint32_t so = (uint32_t)(row * GBSTR + c8 * 8) * 2;
            long go = (long)(k0 + row) * Bstride + N0 + c8 * 8;
            cp16(sB + so, B + go);
        }
    };

    loadStage(0, 0);
    cp_commit();
    loadStage(1, 32);
    cp_commit();

    #pragma unroll 1
    for (int kt = 0; kt < G_NK; kt++) {
        if (kt + 1 < G_NK) cp_wait1(); else cp_wait0();
        __syncthreads();
        if (kt + 2 < G_NK) {
            loadStage((kt + 2) % 3, (kt + 2) * 32);
            cp_commit();
        }

        const uint32_t sA  = sbase + (kt % 3) * G_ST;
        const uint32_t sAl = sA + G_AB;
        const uint32_t sB  = sA + 2 * G_AB;

        #pragma unroll
        for (int kk = 0; kk < 32; kk += 16) {
            uint32_t ah[4][4], al[4][4], bb[2][4];
            #pragma unroll
            for (int i = 0; i < 4; i++) {
                int row = wm * 64 + i * 16 + (lane & 15);
                int colb = (kk + ((lane >> 4) << 3)) * 2;
                uint32_t off = SW64((uint32_t)(row * 64 + colb));
                ldsm_x4(ah[i], sA + off);
                ldsm_x4(al[i], sAl + off);
            }
            #pragma unroll
            for (int jp = 0; jp < 2; jp++) {
                int row = kk + (lane & 15);
                int col = wn * 32 + jp * 16 + ((lane >> 4) << 3);
                uint32_t off = (uint32_t)(row * GBSTR + col) * 2;
                ldsm_x4t(bb[jp], sB + off);
            }
            #pragma unroll
            for (int i = 0; i < 4; i++)
                #pragma unroll
                for (int jp = 0; jp < 2; jp++) {
                    mma_h(c[i][2 * jp],     ah[i], bb[jp]);
                    mma_h(c[i][2 * jp],     al[i], bb[jp]);
                    mma_h(c[i][2 * jp + 1], ah[i], bb[jp] + 2);
                    mma_h(c[i][2 * jp + 1], al[i], bb[jp] + 2);
                }
        }
    }

    // ---- epilogue ----
    float scale = 1.0f;
    __half* dsth = nullptr;
    long dstride = 0, col0 = 0;
    if (EPI == 1) {
        if (N0 < DIM)              { dsth = (__half*)out0; dstride = DIM;   col0 = N0;               scale = 0.125f; }
        else if (N0 < DIM + KVDIM) { dsth = (__half*)out1; dstride = KVDIM; col0 = N0 - DIM;         }
        else                       { dsth = (__half*)out2; dstride = KVDIM; col0 = N0 - DIM - KVDIM; }
    }

    #pragma unroll
    for (int i = 0; i < 4; i++) {
        long r0 = M0 + wm * 64 + i * 16 + (lane >> 2);
        #pragma unroll
        for (int j = 0; j < 4; j++) {
            long cc = wn * 32 + j * 8 + 2 * (lane & 3);
            float v0 = c[i][j][0] * scale, v1 = c[i][j][1] * scale;
            float v2 = c[i][j][2] * scale, v3 = c[i][j][3] * scale;
            if (EPI == 0) {
                float* C = (float*)out0;
                *reinterpret_cast<float2*>(&C[r0 * DIM + N0 + cc])       = make_float2(v0, v1);
                *reinterpret_cast<float2*>(&C[(r0 + 8) * DIM + N0 + cc]) = make_float2(v2, v3);
            } else {
                *reinterpret_cast<uint32_t*>(&dsth[r0 * dstride + col0 + cc])       = packh(v0, v1);
                *reinterpret_cast<uint32_t*>(&dsth[(r0 + 8) * dstride + col0 + cc]) = packh(v2, v3);
            }
        }
    }
}

// ============================================================================
// fp16 flash attention (single-fp16 Q and P; fp32 softmax/accum).
// Block 256 thr (8 warps), 128 q-rows of one (b,h); warp owns 16 rows.
// K/V double-buffered cp.async. Output fp16 hi/lo (exact split).
// ============================================================================
#define TSTR 72
#define Q_BYTES  (128 * TSTR * 2)              // 18432
#define KV_BYTES (64 * TSTR * 2)               //  9216
#define A_STAGE  (2 * KV_BYTES)
#define ATTN_SMEM (Q_BYTES + 2 * A_STAGE)      // 55296

__global__ __launch_bounds__(256) void attn_fp16(
    const __half* __restrict__ Q_g,
    const __half* __restrict__ K_g,  const __half* __restrict__ V_g,
    __half* __restrict__ Oh_g, __half* __restrict__ Ol_g)
{
    extern __shared__ __align__(16) char smp[];
    const uint32_t sb  = smem_u32(smp);
    const uint32_t sQ  = sb;
    const uint32_t sKV = sb + Q_BYTES;

    const int tid  = threadIdx.x;
    const int lane = tid & 31;
    const int warp = tid >> 5;
    const int qt = blockIdx.x, h = blockIdx.y, b = blockIdx.z;
    const int kvh = h >> 2;

    auto loadKV = [&](int st, int kt) {
        uint32_t sK = sKV + st * A_STAGE;
        uint32_t sV = sK + KV_BYTES;
        #pragma unroll
        for (int i = 0; i < 2; i++) {
            int ci = tid + i * 256;
            int row = ci >> 3, c8 = ci & 7;
            uint32_t so = (uint32_t)(row * TSTR + c8 * 8) * 2;
            long go = (long)(b * SEQ + kt * 64 + row) * KVDIM + kvh * HD + c8 * 8;
            cp16(sK + so, K_g + go);
            cp16(sV + so, V_g + go);
        }
    };

    #pragma unroll
    for (int i = 0; i < 4; i++) {
        int ci = tid + i * 256;
        int row = ci >> 3, c8 = ci & 7;
        uint32_t so = (uint32_t)(row * TSTR + c8 * 8) * 2;
        long go = (long)(b * SEQ + qt * 128 + row) * DIM + h * HD + c8 * 8;
        cp16(sQ + so, Q_g + go);
    }
    loadKV(0, 0);
    cp_commit();
    cp_wait0();
    __syncthreads();

    uint32_t qh[4][4];
    #pragma unroll
    for (int t = 0; t < 4; t++) {
        int row = warp * 16 + (lane & 15);
        int col = t * 16 + (lane >> 4) * 8;
        ldsm_x4(qh[t], sQ + (uint32_t)(row * TSTR + col) * 2);
    }

    float o[8][4];
    #pragma unroll
    for (int j = 0; j < 8; j++)
        #pragma unroll
        for (int e = 0; e < 4; e++) o[j][e] = 0.0f;
    float m0v = -1e30f, m1v = -1e30f, l0 = 0.0f, l1 = 0.0f;

    for (int kt = 0; kt < SEQ / 64; kt++) {
        const int cur = kt & 1;
        if (kt + 1 < SEQ / 64) { loadKV(cur ^ 1, kt + 1); }
        cp_commit();

        const uint32_t sK = sKV + cur * A_STAGE;
        const uint32_t sV = sK + KV_BYTES;

        float s[8][4];
        #pragma unroll
        for (int j = 0; j < 8; j++)
            #pragma unroll
            for (int e = 0; e < 4; e++) s[j][e] = 0.0f;

        const int l7 = lane & 7, g4 = lane >> 3;
        #pragma unroll
        for (int t = 0; t < 4; t++) {
            #pragma unroll
            for (int jp = 0; jp < 4; jp++) {
                uint32_t kb[4];
                int row = jp * 16 + ((g4 >> 1) << 3) + l7;
                int col = t * 16 + ((g4 & 1) << 3);
                ldsm_x4(kb, sK + (uint32_t)(row * TSTR + col) * 2);
                mma_h(s[2 * jp],     qh[t], kb);
                mma_h(s[2 * jp + 1], qh[t], kb + 2);
            }
        }

        float tm0 = -1e30f, tm1 = -1e30f;
        #pragma unroll
        for (int j = 0; j < 8; j++) {
            tm0 = fmaxf(tm0, fmaxf(s[j][0], s[j][1]));
            tm1 = fmaxf(tm1, fmaxf(s[j][2], s[j][3]));
        }
        #pragma unroll
        for (int off = 1; off <= 2; off <<= 1) {
            tm0 = fmaxf(tm0, __shfl_xor_sync(0xffffffffu, tm0, off));
            tm1 = fmaxf(tm1, __shfl_xor_sync(0xffffffffu, tm1, off));
        }
        const float mn0 = fmaxf(m0v, tm0), mn1 = fmaxf(m1v, tm1);
        const float a0 = __expf(m0v - mn0), a1 = __expf(m1v - mn1);
        m0v = mn0; m1v = mn1;

        float sum0 = 0.0f, sum1 = 0.0f;
        #pragma unroll
        for (int j = 0; j < 8; j++) {
            s[j][0] = __expf(s[j][0] - mn0);
            s[j][1] = __expf(s[j][1] - mn0);
            s[j][2] = __expf(s[j][2] - mn1);
            s[j][3] = __expf(s[j][3] - mn1);
            sum0 += s[j][0] + s[j][1];
            sum1 += s[j][2] + s[j][3];
        }
        #pragma unroll
        for (int off = 1; off <= 2; off <<= 1) {
            sum0 += __shfl_xor_sync(0xffffffffu, sum0, off);
            sum1 += __shfl_xor_sync(0xffffffffu, sum1, off);
        }
        l0 = l0 * a0 + sum0;
        l1 = l1 * a1 + sum1;
        #pragma unroll
        for (int j = 0; j < 8; j++) {
            o[j][0] *= a0; o[j][1] *= a0;
            o[j][2] *= a1; o[j][3] *= a1;
        }

        #pragma unroll
        for (int t = 0; t < 4; t++) {
            uint32_t ph[4];
            ph[0] = packh(s[2 * t][0],     s[2 * t][1]);
            ph[1] = packh(s[2 * t][2],     s[2 * t][3]);
            ph[2] = packh(s[2 * t + 1][0], s[2 * t + 1][1]);
            ph[3] = packh(s[2 * t + 1][2], s[2 * t + 1][3]);
            #pragma unroll
            for (int jp = 0; jp < 4; jp++) {
                uint32_t vb[4];
                int row = t * 16 + (lane & 15);
                int col = jp * 16 + ((lane >> 4) << 3);
                ldsm_x4t(vb, sV + (uint32_t)(row * TSTR + col) * 2);
                mma_h(o[2 * jp],     ph, vb);
                mma_h(o[2 * jp + 1], ph, vb + 2);
            }
        }

        if (kt + 1 < SEQ / 64) cp_wait0();
        __syncthreads();
    }

    const float il0 = 1.0f / l0, il1 = 1.0f / l1;
    const long base = (long)(b * SEQ + qt * 128 + warp * 16 + (lane >> 2)) * DIM + h * HD;
    #pragma unroll
    for (int j = 0; j < 8; j++) {
        const int col = j * 8 + 2 * (lane & 3);
        float v0 = o[j][0] * il0, v1 = o[j][1] * il0;
        float v2 = o[j][2] * il1, v3 = o[j][3] * il1;
        float h0 = h_round(v0), h1 = h_round(v1);
        float h2 = h_round(v2), h3 = h_round(v3);
        *reinterpret_cast<uint32_t*>(&Oh_g[base + col])            = packh(h0, h1);
        *reinterpret_cast<uint32_t*>(&Oh_g[base + 8L * DIM + col]) = packh(h2, h3);
        *reinterpret_cast<uint32_t*>(&Ol_g[base + col])            = packh(v0 - h0, v1 - h1);
        *reinterpret_cast<uint32_t*>(&Ol_g[base + 8L * DIM + col]) = packh(v2 - h2, v3 - h3);
    }
}

// ============================================================================
// kernel_launch
// ============================================================================
extern "C" void kernel_launch(void* const* d_in, const int* in_sizes, int n_in,
                              void* d_out, int out_size)
{
    const float* x  = (const float*)d_in[0];
    const float* Wq = (const float*)d_in[1];
    const float* Wk = (const float*)d_in[2];
    const float* Wv = (const float*)d_in[3];
    const float* Wo = (const float*)d_in[4];
    float* out = (float*)d_out;

    void *pxh, *pxl, *pwqkv, *pwo, *pQ, *pK, *pV, *pOh, *pOl;
    cudaGetSymbolAddress(&pxh, g_xh);    cudaGetSymbolAddress(&pxl, g_xl);
    cudaGetSymbolAddress(&pwqkv, g_Wqkv); cudaGetSymbolAddress(&pwo, g_Wo);
    cudaGetSymbolAddress(&pQ, g_Q);
    cudaGetSymbolAddress(&pK, g_K);      cudaGetSymbolAddress(&pV, g_V);
    cudaGetSymbolAddress(&pOh, g_Oh);    cudaGetSymbolAddress(&pOl, g_Ol);

    cudaFuncSetAttribute((const void*)gemm_fp16<0>,
                         cudaFuncAttributeMaxDynamicSharedMemorySize, G_SMEM);
    cudaFuncSetAttribute((const void*)gemm_fp16<1>,
                         cudaFuncAttributeMaxDynamicSharedMemorySize, G_SMEM);
    cudaFuncSetAttribute((const void*)attn_fp16,
                         cudaFuncAttributeMaxDynamicSharedMemorySize, ATTN_SMEM);

    // pre-pass: split x; pack Wq|Wk|Wv into [2048][3072]; convert Wo
    split_fp16<<<ROWS * DIM / 1024, 256>>>((const float4*)x,
        (__half*)pxh, (__half*)pxl, ROWS * DIM / 4);
    conv_fp16_strided<<<DIM * DIM / 1024, 256>>>(
        (const float4*)Wq, (__half*)pwqkv, DIM / 4, QKVN, 0, DIM * DIM / 4);
    conv_fp16_strided<<<DIM * KVDIM / 1024, 256>>>(
        (const float4*)Wk, (__half*)pwqkv, KVDIM / 4, QKVN, DIM, DIM * KVDIM / 4);
    conv_fp16_strided<<<DIM * KVDIM / 1024, 256>>>(
        (const float4*)Wv, (__half*)pwqkv, KVDIM / 4, QKVN, DIM + KVDIM, DIM * KVDIM / 4);
    conv_fp16_strided<<<DIM * DIM / 1024, 256>>>(
        (const float4*)Wo, (__half*)pwo, DIM / 4, DIM, 0, DIM * DIM / 4);

    // fused QKV projection: [4096,2048] x [2048,3072]
    gemm_fp16<1><<<dim3(QKVN / 128, ROWS / 128), 256, G_SMEM>>>(
        QKVN, (__half*)pxh, (__half*)pxl, (__half*)pwqkv, pQ, pK, pV);
    // attention -> fp16 hi/lo
    attn_fp16<<<dim3(SEQ / 128, NHEADS, BATCH), 256, ATTN_SMEM>>>(
        (const __half*)pQ, (const __half*)pK, (const __half*)pV,
        (__half*)pOh, (__half*)pOl);
    // out = O @ Wo -> fp32
    gemm_fp16<0><<<dim3(DIM / 128, ROWS / 128), 256, G_SMEM>>>(
        DIM, (__half*)pOh, (__half*)pOl, (__half*)pwo, out, nullptr, nullptr);
}